// round 8
// baseline (speedup 1.0000x reference)
#include <cuda_runtime.h>

// EncodecQuantizer RVQ: x [B,T,D] f32, embed [NQ,K,D] f32 -> codes [NQ,B*T]
// written as float32 (harness output dtype confirmed in R3).
#define BB    16
#define TT    4096
#define DD    128
#define NQ    8
#define KK    1024
#define NTOK  (BB * TT)       // 65536
#define MTILE 128             // tokens per block
#define NTILE 64              // codes per smem tile
#define BLKT  128             // threads per block (16 ty x 8 tx)
#define RSTR  132             // R smem row stride (floats), 16B-aligned rows
#define BSTR  68              // B smem row stride (floats)
#define EPS   3.0e-3f         // fp32 near-tie window -> fp64 recheck

typedef unsigned long long u64;

// smem layout (floats): R[128][RSTR] | Bt[128][BSTR] | bestk[128]
#define SM_R_FLOATS (DD * RSTR)
#define SM_B_FLOATS (DD * BSTR)
#define SMEM_BYTES  ((SM_R_FLOATS + SM_B_FLOATS + MTILE) * 4)

__device__ float g_norms[NQ * KK];

__global__ void norms_kernel(const float* __restrict__ embed) {
    int k = blockIdx.x * blockDim.x + threadIdx.x;
    if (k >= NQ * KK) return;
    const float* e = embed + (size_t)k * DD;
    float s = 0.0f;
#pragma unroll
    for (int i = 0; i < DD; i++) s = fmaf(e[i], e[i], s);
    g_norms[k] = s;
}

// Packed f32x2 FMA (Blackwell): acc += a * b per 32-bit lane.
#define FMA2(acc, av, bv) \
    asm("fma.rn.f32x2 %0, %1, %2, %0;" : "+l"(acc) : "l"(av), "l"(bv))
// Duplicate one fp32 into both lanes of a u64.
#define DUP2(dst, f) \
    asm("mov.b64 %0, {%1, %1};" : "=l"(dst) : "f"(f))

__device__ __forceinline__ float lo32(u64 a) {
    return __uint_as_float((unsigned int)(a & 0xffffffffull));
}
__device__ __forceinline__ float hi32(u64 a) {
    return __uint_as_float((unsigned int)(a >> 32));
}

// Exact (fp64) distance for token column of smem R vs codeword e (global).
__device__ double dist_exact_col(const float* __restrict__ R, int tok,
                                 const float* __restrict__ e) {
    double dot = 0.0, nrm = 0.0;
#pragma unroll 4
    for (int d = 0; d < DD; d++) {
        double r = (double)R[d * RSTR + tok];
        double v = (double)__ldg(e + d);
        dot += r * v;
        nrm += v * v;
    }
    return 2.0 * dot - nrm;
}

// ---------------------------------------------------------------------------
// Register-tiled RVQ, 8x8 per-thread micro-tile (codes packed in f32x2 pairs):
// per k: 4 LDS.128 + 8 dup-movs feed 32 FMA2 (8:1 fma:lds ratio). Block owns
// 128 tokens (residual in smem [d][tok]); codebook streamed in 64-code tiles.
// Per-token top-2 merged across 8 code lanes; near-ties recomputed in fp64.
// ---------------------------------------------------------------------------
__global__ void __launch_bounds__(BLKT, 2)
rvq_kernel(const float* __restrict__ x,
           const float* __restrict__ embed,
           float* __restrict__ codes) {
    extern __shared__ float sm[];
    float* R  = sm;                          // [DD][RSTR]
    float* Bt = sm + SM_R_FLOATS;            // [DD][BSTR]
    int*   bk = (int*)(sm + SM_R_FLOATS + SM_B_FLOATS);  // [MTILE]

    const int tid = threadIdx.x;
    const int tx  = tid & 7;      // code-lane  (8 codes each)
    const int ty  = tid >> 3;     // token-lane (8 tokens each, 0..15)
    const int tok0 = blockIdx.x * MTILE;

    // ---- Load x -> R transposed ([d][tok]); 1 thread per token ----
    {
        const float4* xr =
            reinterpret_cast<const float4*>(x + (size_t)(tok0 + tid) * DD);
#pragma unroll
        for (int j = 0; j < DD / 4; j++) {
            float4 v = xr[j];
            int d = j * 4;
            R[(d + 0) * RSTR + tid] = v.x;
            R[(d + 1) * RSTR + tid] = v.y;
            R[(d + 2) * RSTR + tid] = v.z;
            R[(d + 3) * RSTR + tid] = v.w;
        }
    }
    __syncthreads();

    for (int s = 0; s < NQ; s++) {
        const float* es = embed + (size_t)s * KK * DD;

        // per-token top-2 (8 tokens per thread, over this thread's codes)
        float d1[8], d2v[8];
        int   k1[8], k2[8];
#pragma unroll
        for (int i = 0; i < 8; i++) {
            d1[i] = -3.402823466e+38f; d2v[i] = -3.402823466e+38f;
            k1[i] = 0; k2[i] = 0;
        }

        for (int t = 0; t < KK / NTILE; t++) {
            __syncthreads();   // previous tile's readers done
            // ---- Load code tile -> Bt transposed ([d][code]) ----
            {
                int code = tid >> 1;           // 0..63
                int dh   = (tid & 1) * 64;     // 64 dims each
                const float* eg = es + (size_t)(t * NTILE + code) * DD + dh;
#pragma unroll
                for (int j = 0; j < 16; j++) {
                    float4 v = *reinterpret_cast<const float4*>(eg + j * 4);
                    int d = dh + j * 4;
                    Bt[(d + 0) * BSTR + code] = v.x;
                    Bt[(d + 1) * BSTR + code] = v.y;
                    Bt[(d + 2) * BSTR + code] = v.z;
                    Bt[(d + 3) * BSTR + code] = v.w;
                }
            }
            __syncthreads();

            // ---- 8x8 micro-GEMM over K=128; codes packed in pairs ----
            u64 acc[32];   // [tok 0..7][code-pair 0..3]
#pragma unroll
            for (int i = 0; i < 32; i++) acc[i] = 0ull;

            const float* ra = R + ty * 8;
            const float* rb = Bt + tx * 8;
#pragma unroll 4
            for (int k = 0; k < DD; k++) {
                float4 r0 = *reinterpret_cast<const float4*>(ra + k * RSTR);
                float4 r1 = *reinterpret_cast<const float4*>(ra + k * RSTR + 4);
                ulonglong2 b01 =
                    *reinterpret_cast<const ulonglong2*>(rb + k * BSTR);
                ulonglong2 b23 =
                    *reinterpret_cast<const ulonglong2*>(rb + k * BSTR + 4);
                u64 rd[8];
                DUP2(rd[0], r0.x); DUP2(rd[1], r0.y);
                DUP2(rd[2], r0.z); DUP2(rd[3], r0.w);
                DUP2(rd[4], r1.x); DUP2(rd[5], r1.y);
                DUP2(rd[6], r1.z); DUP2(rd[7], r1.w);
#pragma unroll
                for (int m = 0; m < 8; m++) {
                    FMA2(acc[m * 4 + 0], rd[m], b01.x);
                    FMA2(acc[m * 4 + 1], rd[m], b01.y);
                    FMA2(acc[m * 4 + 2], rd[m], b23.x);
                    FMA2(acc[m * 4 + 3], rd[m], b23.y);
                }
            }

            // ---- Epilogue: distances + top-2 (ascending code order) ----
            int kb0 = t * NTILE + tx * 8;
#pragma unroll
            for (int cp = 0; cp < 4; cp++) {
                float n0 = __ldg(&g_norms[s * KK + kb0 + cp * 2]);
                float n1 = __ldg(&g_norms[s * KK + kb0 + cp * 2 + 1]);
                int kc0 = kb0 + cp * 2, kc1 = kc0 + 1;
#pragma unroll
                for (int m = 0; m < 8; m++) {
                    u64 a = acc[m * 4 + cp];
                    float dl = 2.0f * lo32(a) - n0;   // code kc0
                    float dh = 2.0f * hi32(a) - n1;   // code kc1
                    if (dl > d1[m]) {
                        d2v[m] = d1[m]; k2[m] = k1[m];
                        d1[m] = dl; k1[m] = kc0;
                    } else if (dl > d2v[m]) { d2v[m] = dl; k2[m] = kc0; }
                    if (dh > d1[m]) {
                        d2v[m] = d1[m]; k2[m] = k1[m];
                        d1[m] = dh; k1[m] = kc1;
                    } else if (dh > d2v[m]) { d2v[m] = dh; k2[m] = kc1; }
                }
            }
        }

        // ---- Merge top-2 across 8 code lanes (xor within tx group) ----
#pragma unroll
        for (int m = 1; m < 8; m <<= 1) {
#pragma unroll
            for (int i = 0; i < 8; i++) {
                float od1 = __shfl_xor_sync(0xffffffffu, d1[i], m);
                int   ok1 = __shfl_xor_sync(0xffffffffu, k1[i], m);
                float od2 = __shfl_xor_sync(0xffffffffu, d2v[i], m);
                int   ok2 = __shfl_xor_sync(0xffffffffu, k2[i], m);
                bool ob = (od1 > d1[i]) || (od1 == d1[i] && ok1 < k1[i]);
                if (ob) {
                    bool sb = (d1[i] > od2) || (d1[i] == od2 && k1[i] < ok2);
                    d2v[i] = sb ? d1[i] : od2;
                    k2[i]  = sb ? k1[i] : ok2;
                    d1[i] = od1; k1[i] = ok1;
                } else {
                    bool sb = (od1 > d2v[i]) || (od1 == d2v[i] && ok1 < k2[i]);
                    if (sb) { d2v[i] = od1; k2[i] = ok1; }
                }
            }
        }

        // ---- Finalize per token (tx==0), exact recheck on near-ties ----
        if (tx == 0) {
#pragma unroll 1
            for (int i = 0; i < 8; i++) {
                int tok = ty * 8 + i;
                int kbest = k1[i];
                if (d1[i] - d2v[i] <= EPS) {
                    double e1 = dist_exact_col(R, tok, es + (size_t)k1[i] * DD);
                    double e2 = dist_exact_col(R, tok, es + (size_t)k2[i] * DD);
                    if (e2 > e1 || (e2 == e1 && k2[i] < k1[i])) kbest = k2[i];
                }
                bk[tok] = kbest;
            }
        }
        __syncthreads();

        // ---- Emit codes + residual update (1 thread per token) ----
        {
            int kb2 = bk[tid];
            codes[(size_t)s * NTOK + tok0 + tid] = (float)kb2;
            const float4* eb =
                reinterpret_cast<const float4*>(es + (size_t)kb2 * DD);
#pragma unroll
            for (int j = 0; j < DD / 4; j++) {
                float4 v = eb[j];
                int d = j * 4;
                R[(d + 0) * RSTR + tid] -= v.x;
                R[(d + 1) * RSTR + tid] -= v.y;
                R[(d + 2) * RSTR + tid] -= v.z;
                R[(d + 3) * RSTR + tid] -= v.w;
            }
        }
        __syncthreads();
    }
}

extern "C" void kernel_launch(void* const* d_in, const int* in_sizes, int n_in,
                              void* d_out, int out_size) {
    const float* p0 = (const float*)d_in[0];
    const float* p1 = (const float*)d_in[1];
    const float* x;
    const float* embed;
    if (in_sizes[0] > in_sizes[1]) { x = p0; embed = p1; }
    else                           { x = p1; embed = p0; }
    float* codes = (float*)d_out;

    cudaFuncSetAttribute(rvq_kernel,
                         cudaFuncAttributeMaxDynamicSharedMemorySize,
                         SMEM_BYTES);

    norms_kernel<<<(NQ * KK + 255) / 256, 256>>>(embed);
    rvq_kernel<<<NTOK / MTILE, BLKT, SMEM_BYTES>>>(x, embed, codes);
}

// round 10
// speedup vs baseline: 1.9680x; 1.9680x over previous
#include <cuda_runtime.h>
#include <cuda_bf16.h>
#include <cstdint>

// EncodecQuantizer RVQ via mma.sync bf16x3 (emulated-fp32) GEMM.
// x [B,T,D] f32, embed [NQ,K,D] f32 -> codes [NQ,B*T] as float32.
#define BB    16
#define TT    4096
#define DD    128
#define NQ    8
#define KK    1024
#define NTOK  (BB * TT)        // 65536
#define MT    128              // tokens per block
#define NT    64               // codes per tile
#define BLKT  256              // 8 warps
#define RSTR  132              // R smem row stride (floats)
#define ASTR_B 528             // A/B smem row stride in BYTES (264 bf16)
#define EPS   3.0e-3f
#define FLTMIN (-3.402823466e+38f)

typedef unsigned long long u64;
typedef unsigned int u32;
typedef unsigned short u16;

// smem byte offsets
#define SM_A   0                                   // 128 x 264 bf16 = 67584
#define SM_B   (SM_A + MT * ASTR_B)                // 64 x 264 bf16 = 33792
#define SM_R   (SM_B + NT * ASTR_B)                // 128 x 132 f32 = 67584
#define SM_N   (SM_R + MT * RSTR * 4)              // 1024 f32 = 4096
#define SM_BK  (SM_N + KK * 4)                     // 128 int
#define SMEM_BYTES (SM_BK + MT * 4)                // 173568

__device__ float g_norms[NQ * KK];
// per codeword: e1[0..127] then e2[0..127] (bf16 hi/lo split)
__device__ __nv_bfloat16 g_esplit[(size_t)NQ * KK * 256];

// ---------------------------------------------------------------------------
__global__ void prep_kernel(const float* __restrict__ embed) {
    int k = blockIdx.x * blockDim.x + threadIdx.x;
    if (k >= NQ * KK) return;
    const float* e = embed + (size_t)k * DD;
    __nv_bfloat16* o = g_esplit + (size_t)k * 256;
    float s = 0.0f;
#pragma unroll 4
    for (int d = 0; d < DD; d++) {
        float v = e[d];
        s = fmaf(v, v, s);
        __nv_bfloat16 b1 = __float2bfloat16_rn(v);
        __nv_bfloat16 b2 = __float2bfloat16_rn(v - __bfloat162float(b1));
        o[d] = b1;
        o[DD + d] = b2;
    }
    g_norms[k] = s;
}

// ---------------------------------------------------------------------------
__device__ __forceinline__ u32 smem_u32(const void* p) {
    u32 a;
    asm("{ .reg .u64 t; cvta.to.shared.u64 t, %1; cvt.u32.u64 %0, t; }"
        : "=r"(a) : "l"(p));
    return a;
}
__device__ __forceinline__ void ldsm_x4(u32& r0, u32& r1, u32& r2, u32& r3,
                                        u32 addr) {
    asm volatile("ldmatrix.sync.aligned.m8n8.x4.shared.b16 {%0,%1,%2,%3}, [%4];"
                 : "=r"(r0), "=r"(r1), "=r"(r2), "=r"(r3) : "r"(addr));
}
__device__ __forceinline__ void mma_bf16(float* c, u32 a0, u32 a1, u32 a2,
                                         u32 a3, u32 b0, u32 b1) {
    asm volatile(
        "mma.sync.aligned.m16n8k16.row.col.f32.bf16.bf16.f32 "
        "{%0,%1,%2,%3}, {%4,%5,%6,%7}, {%8,%9}, {%0,%1,%2,%3};"
        : "+f"(c[0]), "+f"(c[1]), "+f"(c[2]), "+f"(c[3])
        : "r"(a0), "r"(a1), "r"(a2), "r"(a3), "r"(b0), "r"(b1));
}

// top-2 update, ascending-code encounter order assumed
#define UPD(d1, d2, q1, q2, dist, kc)                                    \
    do {                                                                 \
        if ((dist) > (d1)) { (d2) = (d1); (q2) = (q1); (d1) = (dist);    \
                             (q1) = (kc); }                              \
        else if ((dist) > (d2)) { (d2) = (dist); (q2) = (kc); }          \
    } while (0)

// merge other's top2 (od1,ok1,od2,ok2) into ours; lower index wins ties
#define MERGE(d1, q1, d2, q2, od1, ok1, od2, ok2)                        \
    do {                                                                 \
        bool ob = ((od1) > (d1)) || ((od1) == (d1) && (ok1) < (q1));     \
        if (ob) {                                                        \
            bool sb = ((d1) > (od2)) || ((d1) == (od2) && (q1) < (ok2)); \
            (d2) = sb ? (d1) : (od2); (q2) = sb ? (q1) : (ok2);          \
            (d1) = (od1); (q1) = (ok1);                                  \
        } else {                                                         \
            bool sb = ((od1) > (d2)) || ((od1) == (d2) && (ok1) < (q2)); \
            if (sb) { (d2) = (od1); (q2) = (ok1); }                      \
        }                                                                \
    } while (0)

// ---------------------------------------------------------------------------
// Block = 128 tokens; warp w owns token rows [w*16, w*16+16). Per stage:
// rebuild A (bf16 split of residual), stream 16 B-tiles of 64 codes,
// mma.sync K=384 ([r1,r1,r2] x [e1,e2,e1] via address mapping), top-2 in
// C-fragments, quad-shuffle merge, fp64 near-tie recheck, residual update.
// ---------------------------------------------------------------------------
__global__ void __launch_bounds__(BLKT, 1)
rvq_mma_kernel(const float* __restrict__ x,
               const float* __restrict__ embed,
               float* __restrict__ codes) {
    extern __shared__ __align__(16) unsigned char smraw[];
    float* R  = (float*)(smraw + SM_R);
    float* SN = (float*)(smraw + SM_N);
    int*   bk = (int*)(smraw + SM_BK);
    const u32 smb = smem_u32(smraw);

    const int tid  = threadIdx.x;
    const int lane = tid & 31;
    const int wid  = tid >> 5;
    const int tok0 = blockIdx.x * MT;

    // ---- x -> R ----
    {
        int row = tid >> 1, half = tid & 1;
        const float4* xs = (const float4*)(x + (size_t)(tok0 + row) * DD +
                                           half * 64);
        float4* rd = (float4*)(R + row * RSTR + half * 64);
#pragma unroll
        for (int j = 0; j < 16; j++) rd[j] = xs[j];
    }
    __syncthreads();

    // precomputed lane addressing
    const int a_row  = wid * 16 + (lane & 15);
    const int a_cadd = ((lane >> 4) << 3) * 2;      // +8 cols (bytes)
    const int b_nloc = ((lane >> 4) << 3) | (lane & 7);
    const int b_cadd = (lane & 8) ? 16 : 0;         // +8 cols (bytes)

    for (int s = 0; s < NQ; s++) {
        const float* es = embed + (size_t)s * KK * DD;

        // stage norms
        for (int i = tid; i < KK; i += BLKT) SN[i] = g_norms[s * KK + i];

        // ---- A rebuild: bf16 split of residual (store r1 cols 0-127, r2 128-255)
        {
            int row = tid >> 1, half = tid & 1;
            const float4* r = (const float4*)(R + row * RSTR + half * 64);
            unsigned char* abase = smraw + SM_A + row * ASTR_B + half * 128;
#pragma unroll
            for (int j = 0; j < 16; j++) {
                float4 v = r[j];
                float vf[4] = {v.x, v.y, v.z, v.w};
                u16 h1[4], h2[4];
#pragma unroll
                for (int q = 0; q < 4; q++) {
                    __nv_bfloat16 b1 = __float2bfloat16_rn(vf[q]);
                    __nv_bfloat16 b2 =
                        __float2bfloat16_rn(vf[q] - __bfloat162float(b1));
                    h1[q] = __bfloat16_as_ushort(b1);
                    h2[q] = __bfloat16_as_ushort(b2);
                }
                uint2 w1 = make_uint2((u32)h1[0] | ((u32)h1[1] << 16),
                                      (u32)h1[2] | ((u32)h1[3] << 16));
                uint2 w2 = make_uint2((u32)h2[0] | ((u32)h2[1] << 16),
                                      (u32)h2[2] | ((u32)h2[3] << 16));
                *(uint2*)(abase + j * 8) = w1;         // r1 at col d
                *(uint2*)(abase + 256 + j * 8) = w2;   // r2 at col 128+d
            }
        }

        // per-thread top-2 for two token rows (lane/4 and lane/4+8 of warp)
        float d1a = FLTMIN, d2a = FLTMIN, d1b = FLTMIN, d2b = FLTMIN;
        int   k1a = 0, k2a = 0, k1b = 0, k2b = 0;

        for (int t = 0; t < 16; t++) {
            __syncthreads();   // A ready (t=0) / previous tile consumers done
            // ---- load B tile: 64 codes x 512 B ----
            {
                const uint4* src = (const uint4*)(g_esplit +
                    ((size_t)s * KK + (size_t)t * NT) * 256);
#pragma unroll
                for (int i = 0; i < 8; i++) {
                    int idx = tid + i * BLKT;
                    int rb = idx >> 5, u = idx & 31;
                    *(uint4*)(smraw + SM_B + rb * ASTR_B + u * 16) = src[idx];
                }
            }
            __syncthreads();

            float acc[8][4];
#pragma unroll
            for (int i = 0; i < 8; i++) {
                acc[i][0] = 0.f; acc[i][1] = 0.f;
                acc[i][2] = 0.f; acc[i][3] = 0.f;
            }

            // K = 384: blocks A=[r1,r1,r2], B=[e1,e2,e1] via column mapping
#pragma unroll 4
            for (int ks = 0; ks < 24; ks++) {
                int acol = (ks < 8) ? ks * 16
                         : (ks < 16) ? (ks - 8) * 16 : 128 + (ks - 16) * 16;
                int bcol = (ks < 8) ? ks * 16
                         : (ks < 16) ? 128 + (ks - 8) * 16 : (ks - 16) * 16;
                u32 a0, a1, a2, a3;
                ldsm_x4(a0, a1, a2, a3,
                        smb + SM_A + a_row * ASTR_B + acol * 2 + a_cadd);
#pragma unroll
                for (int np = 0; np < 4; np++) {
                    u32 b0, b1, b2, b3;
                    ldsm_x4(b0, b1, b2, b3,
                            smb + SM_B + (np * 16 + b_nloc) * ASTR_B +
                            bcol * 2 + b_cadd);
                    mma_bf16(acc[np * 2 + 0], a0, a1, a2, a3, b0, b1);
                    mma_bf16(acc[np * 2 + 1], a0, a1, a2, a3, b2, b3);
                }
            }

            // ---- epilogue: distances + top-2 ----
#pragma unroll
            for (int nb = 0; nb < 8; nb++) {
                int kc = t * NT + nb * 8 + (lane & 3) * 2;
                float n0 = SN[kc], n1 = SN[kc + 1];
                UPD(d1a, d2a, k1a, k2a, 2.0f * acc[nb][0] - n0, kc);
                UPD(d1a, d2a, k1a, k2a, 2.0f * acc[nb][1] - n1, kc + 1);
                UPD(d1b, d2b, k1b, k2b, 2.0f * acc[nb][2] - n0, kc);
                UPD(d1b, d2b, k1b, k2b, 2.0f * acc[nb][3] - n1, kc + 1);
            }
        }

        // ---- merge across the 4 lanes of each quad ----
#pragma unroll
        for (int m = 1; m < 4; m <<= 1) {
            float od1 = __shfl_xor_sync(0xffffffffu, d1a, m);
            int   ok1 = __shfl_xor_sync(0xffffffffu, k1a, m);
            float od2 = __shfl_xor_sync(0xffffffffu, d2a, m);
            int   ok2 = __shfl_xor_sync(0xffffffffu, k2a, m);
            MERGE(d1a, k1a, d2a, k2a, od1, ok1, od2, ok2);
            od1 = __shfl_xor_sync(0xffffffffu, d1b, m);
            ok1 = __shfl_xor_sync(0xffffffffu, k1b, m);
            od2 = __shfl_xor_sync(0xffffffffu, d2b, m);
            ok2 = __shfl_xor_sync(0xffffffffu, k2b, m);
            MERGE(d1b, k1b, d2b, k2b, od1, ok1, od2, ok2);
        }

        // ---- finalize (quad leader), fp64 recheck on near-ties ----
        if ((lane & 3) == 0) {
            int tA = wid * 16 + (lane >> 2);
#pragma unroll
            for (int h = 0; h < 2; h++) {
                int tok  = tA + h * 8;
                float f1 = h ? d1b : d1a, f2 = h ? d2b : d2a;
                int   c1 = h ? k1b : k1a, c2 = h ? k2b : k2a;
                int kbest = c1;
                if (f1 - f2 <= EPS) {
                    const float* r = R + tok * RSTR;
                    const float* e1p = es + (size_t)c1 * DD;
                    const float* e2p = es + (size_t)c2 * DD;
                    double q1 = 0.0, q2 = 0.0;
#pragma unroll 4
                    for (int d = 0; d < DD; d++) {
                        double rv = (double)r[d];
                        double a = (double)__ldg(e1p + d);
                        double b = (double)__ldg(e2p + d);
                        q1 += rv * a - 0.5 * a * a;
                        q2 += rv * b - 0.5 * b * b;
                    }
                    if (q2 > q1 || (q2 == q1 && c2 < c1)) kbest = c2;
                }
                bk[tok] = kbest;
            }
        }
        __syncthreads();

        // ---- emit codes + residual update ----
        if (tid < MT) {
            int kb2 = bk[tid];
            codes[(size_t)s * NTOK + tok0 + tid] = (float)kb2;
            const float4* eb = (const float4*)(es + (size_t)kb2 * DD);
            float4* rr = (float4*)(R + tid * RSTR);
#pragma unroll 8
            for (int j = 0; j < DD / 4; j++) {
                float4 rv = rr[j], ev = eb[j];
                rv.x -= ev.x; rv.y -= ev.y; rv.z -= ev.z; rv.w -= ev.w;
                rr[j] = rv;
            }
        }
        __syncthreads();
    }
}

// ---------------------------------------------------------------------------
extern "C" void kernel_launch(void* const* d_in, const int* in_sizes, int n_in,
                              void* d_out, int out_size) {
    const float* p0 = (const float*)d_in[0];
    const float* p1 = (const float*)d_in[1];
    const float* x;
    const float* embed;
    if (in_sizes[0] > in_sizes[1]) { x = p0; embed = p1; }
    else                           { x = p1; embed = p0; }
    float* codes = (float*)d_out;

    cudaFuncSetAttribute(rvq_mma_kernel,
                         cudaFuncAttributeMaxDynamicSharedMemorySize,
                         SMEM_BYTES);

    prep_kernel<<<(NQ * KK + 127) / 128, 128>>>(embed);
    rvq_mma_kernel<<<NTOK / MT, BLKT, SMEM_BYTES>>>(x, embed, codes);
}

// round 11
// speedup vs baseline: 2.0037x; 1.0182x over previous
#include <cuda_runtime.h>
#include <cuda_bf16.h>
#include <cstdint>

// EncodecQuantizer RVQ via mma.sync bf16x3 (emulated-fp32) GEMM,
// double-buffered cp.async B-stream.
// x [B,T,D] f32, embed [NQ,K,D] f32 -> codes [NQ,B*T] as float32.
#define BB    16
#define TT    4096
#define DD    128
#define NQ    8
#define KK    1024
#define NTOK  (BB * TT)        // 65536
#define MT    128              // tokens per block
#define NT    64               // codes per tile
#define NTILES (KK / NT)       // 16
#define BLKT  256              // 8 warps
#define RSTR  132              // R smem row stride (floats)
#define ASTR_B 528             // A/B smem row stride in BYTES (264 bf16)
#define EPS   3.0e-3f
#define FLTMIN (-3.402823466e+38f)

typedef unsigned long long u64;
typedef unsigned int u32;
typedef unsigned short u16;

// smem byte offsets
#define SM_A   0                                   // 128 x 264 bf16 = 67584
#define SM_B0  (SM_A + MT * ASTR_B)                // 64 x 528 B     = 33792
#define SM_B1  (SM_B0 + NT * ASTR_B)               // second buffer
#define SM_R   (SM_B1 + NT * ASTR_B)               // 128 x 132 f32  = 67584
#define SM_N   (SM_R + MT * RSTR * 4)              // 1024 f32
#define SM_BK  (SM_N + KK * 4)                     // 128 int
#define SMEM_BYTES (SM_BK + MT * 4)                // 207360

__device__ float g_norms[NQ * KK];
// per codeword: e1[0..127] then e2[0..127] (bf16 hi/lo split)
__device__ __nv_bfloat16 g_esplit[(size_t)NQ * KK * 256];

// ---------------------------------------------------------------------------
__global__ void prep_kernel(const float* __restrict__ embed) {
    int k = blockIdx.x * blockDim.x + threadIdx.x;
    if (k >= NQ * KK) return;
    const float* e = embed + (size_t)k * DD;
    __nv_bfloat16* o = g_esplit + (size_t)k * 256;
    float s = 0.0f;
#pragma unroll 4
    for (int d = 0; d < DD; d++) {
        float v = e[d];
        s = fmaf(v, v, s);
        __nv_bfloat16 b1 = __float2bfloat16_rn(v);
        __nv_bfloat16 b2 = __float2bfloat16_rn(v - __bfloat162float(b1));
        o[d] = b1;
        o[DD + d] = b2;
    }
    g_norms[k] = s;
}

// ---------------------------------------------------------------------------
__device__ __forceinline__ u32 smem_u32(const void* p) {
    u32 a;
    asm("{ .reg .u64 t; cvta.to.shared.u64 t, %1; cvt.u32.u64 %0, t; }"
        : "=r"(a) : "l"(p));
    return a;
}
__device__ __forceinline__ void ldsm_x4(u32& r0, u32& r1, u32& r2, u32& r3,
                                        u32 addr) {
    asm volatile("ldmatrix.sync.aligned.m8n8.x4.shared.b16 {%0,%1,%2,%3}, [%4];"
                 : "=r"(r0), "=r"(r1), "=r"(r2), "=r"(r3) : "r"(addr));
}
__device__ __forceinline__ void mma_bf16(float* c, u32 a0, u32 a1, u32 a2,
                                         u32 a3, u32 b0, u32 b1) {
    asm volatile(
        "mma.sync.aligned.m16n8k16.row.col.f32.bf16.bf16.f32 "
        "{%0,%1,%2,%3}, {%4,%5,%6,%7}, {%8,%9}, {%0,%1,%2,%3};"
        : "+f"(c[0]), "+f"(c[1]), "+f"(c[2]), "+f"(c[3])
        : "r"(a0), "r"(a1), "r"(a2), "r"(a3), "r"(b0), "r"(b1));
}
__device__ __forceinline__ void cp16(u32 dst_smem, const void* src) {
    asm volatile("cp.async.cg.shared.global [%0], [%1], 16;"
                 :: "r"(dst_smem), "l"(src));
}
#define CP_COMMIT() asm volatile("cp.async.commit_group;" ::: "memory")
#define CP_WAIT0()  asm volatile("cp.async.wait_group 0;" ::: "memory")

// top-2 update, ascending-code encounter order assumed
#define UPD(d1, d2, q1, q2, dist, kc)                                    \
    do {                                                                 \
        if ((dist) > (d1)) { (d2) = (d1); (q2) = (q1); (d1) = (dist);    \
                             (q1) = (kc); }                              \
        else if ((dist) > (d2)) { (d2) = (dist); (q2) = (kc); }          \
    } while (0)

// merge other's top2 into ours; lower index wins ties
#define MERGE(d1, q1, d2, q2, od1, ok1, od2, ok2)                        \
    do {                                                                 \
        bool ob = ((od1) > (d1)) || ((od1) == (d1) && (ok1) < (q1));     \
        if (ob) {                                                        \
            bool sb = ((d1) > (od2)) || ((d1) == (od2) && (q1) < (ok2)); \
            (d2) = sb ? (d1) : (od2); (q2) = sb ? (q1) : (ok2);          \
            (d1) = (od1); (q1) = (ok1);                                  \
        } else {                                                         \
            bool sb = ((od1) > (d2)) || ((od1) == (d2) && (ok1) < (q2)); \
            if (sb) { (d2) = (od1); (q2) = (ok1); }                      \
        }                                                                \
    } while (0)

// ---------------------------------------------------------------------------
__global__ void __launch_bounds__(BLKT, 1)
rvq_mma_kernel(const float* __restrict__ x,
               const float* __restrict__ embed,
               float* __restrict__ codes) {
    extern __shared__ __align__(16) unsigned char smraw[];
    float* R  = (float*)(smraw + SM_R);
    float* SN = (float*)(smraw + SM_N);
    int*   bk = (int*)(smraw + SM_BK);
    const u32 smb = smem_u32(smraw);

    const int tid  = threadIdx.x;
    const int lane = tid & 31;
    const int wid  = tid >> 5;
    const int tok0 = blockIdx.x * MT;

    // ---- x -> R ----
    {
        int row = tid >> 1, half = tid & 1;
        const float4* xs = (const float4*)(x + (size_t)(tok0 + row) * DD +
                                           half * 64);
        float4* rd = (float4*)(R + row * RSTR + half * 64);
#pragma unroll
        for (int j = 0; j < 16; j++) rd[j] = xs[j];
    }
    __syncthreads();

    // lane addressing for ldmatrix
    const int a_row  = wid * 16 + (lane & 15);
    const int a_cadd = ((lane >> 4) << 3) * 2;      // +8 cols (bytes)
    const int b_nloc = ((lane >> 4) << 3) | (lane & 7);
    const int b_cadd = (lane & 8) ? 16 : 0;         // +8 cols (bytes)
    const u32 buf_off[2] = {SM_B0, SM_B1};

    for (int s = 0; s < NQ; s++) {
        const float* es = embed + (size_t)s * KK * DD;
        const uint4* bsrc =
            (const uint4*)(g_esplit + (size_t)s * KK * 256);

        // stage norms
        for (int i = tid; i < KK; i += BLKT) SN[i] = g_norms[s * KK + i];

        // ---- A rebuild: bf16 split of residual ----
        {
            int row = tid >> 1, half = tid & 1;
            const float4* r = (const float4*)(R + row * RSTR + half * 64);
            unsigned char* abase = smraw + SM_A + row * ASTR_B + half * 128;
#pragma unroll
            for (int j = 0; j < 16; j++) {
                float4 v = r[j];
                float vf[4] = {v.x, v.y, v.z, v.w};
                u16 h1[4], h2[4];
#pragma unroll
                for (int q = 0; q < 4; q++) {
                    __nv_bfloat16 b1 = __float2bfloat16_rn(vf[q]);
                    __nv_bfloat16 b2 =
                        __float2bfloat16_rn(vf[q] - __bfloat162float(b1));
                    h1[q] = __bfloat16_as_ushort(b1);
                    h2[q] = __bfloat16_as_ushort(b2);
                }
                uint2 w1 = make_uint2((u32)h1[0] | ((u32)h1[1] << 16),
                                      (u32)h1[2] | ((u32)h1[3] << 16));
                uint2 w2 = make_uint2((u32)h2[0] | ((u32)h2[1] << 16),
                                      (u32)h2[2] | ((u32)h2[3] << 16));
                *(uint2*)(abase + j * 8) = w1;         // r1 at col d
                *(uint2*)(abase + 256 + j * 8) = w2;   // r2 at col 128+d
            }
        }

        // ---- prologue: async-load B tile 0 ----
        {
            int rb = tid >> 5, u = tid & 31;   // 8 iters via stride
#pragma unroll
            for (int i = 0; i < 8; i++) {
                int idx = tid + i * BLKT;
                int r2 = idx >> 5, u2 = idx & 31;
                cp16(smb + SM_B0 + r2 * ASTR_B + u2 * 16,
                     bsrc + (size_t)r2 * 32 + u2);
            }
            (void)rb; (void)u;
        }
        CP_COMMIT();
        CP_WAIT0();
        __syncthreads();   // A + B0 visible to all warps

        float d1a = FLTMIN, d2a = FLTMIN, d1b = FLTMIN, d2b = FLTMIN;
        int   k1a = 0, k2a = 0, k1b = 0, k2b = 0;

        for (int t = 0; t < NTILES; t++) {
            const u32 cur = buf_off[t & 1];
            // ---- issue async load of next tile (overlaps with MMA below) ----
            if (t + 1 < NTILES) {
                const uint4* src = bsrc + (size_t)(t + 1) * NT * 32;
                const u32 nxt = buf_off[(t + 1) & 1];
#pragma unroll
                for (int i = 0; i < 8; i++) {
                    int idx = tid + i * BLKT;
                    int r2 = idx >> 5, u2 = idx & 31;
                    cp16(smb + nxt + r2 * ASTR_B + u2 * 16,
                         src + (size_t)r2 * 32 + u2);
                }
                CP_COMMIT();
            }

            // ---- MMA on current tile ----
            float acc[8][4];
#pragma unroll
            for (int i = 0; i < 8; i++) {
                acc[i][0] = 0.f; acc[i][1] = 0.f;
                acc[i][2] = 0.f; acc[i][3] = 0.f;
            }
#pragma unroll 4
            for (int ks = 0; ks < 24; ks++) {
                int acol = (ks < 8) ? ks * 16
                         : (ks < 16) ? (ks - 8) * 16 : 128 + (ks - 16) * 16;
                int bcol = (ks < 8) ? ks * 16
                         : (ks < 16) ? 128 + (ks - 8) * 16 : (ks - 16) * 16;
                u32 a0, a1, a2, a3;
                ldsm_x4(a0, a1, a2, a3,
                        smb + SM_A + a_row * ASTR_B + acol * 2 + a_cadd);
#pragma unroll
                for (int np = 0; np < 4; np++) {
                    u32 b0, b1, b2, b3;
                    ldsm_x4(b0, b1, b2, b3,
                            smb + cur + (np * 16 + b_nloc) * ASTR_B +
                            bcol * 2 + b_cadd);
                    mma_bf16(acc[np * 2 + 0], a0, a1, a2, a3, b0, b1);
                    mma_bf16(acc[np * 2 + 1], a0, a1, a2, a3, b2, b3);
                }
            }

            // ---- epilogue: distances + top-2 ----
#pragma unroll
            for (int nb = 0; nb < 8; nb++) {
                int kc = t * NT + nb * 8 + (lane & 3) * 2;
                float n0 = SN[kc], n1 = SN[kc + 1];
                UPD(d1a, d2a, k1a, k2a, 2.0f * acc[nb][0] - n0, kc);
                UPD(d1a, d2a, k1a, k2a, 2.0f * acc[nb][1] - n1, kc + 1);
                UPD(d1b, d2b, k1b, k2b, 2.0f * acc[nb][2] - n0, kc);
                UPD(d1b, d2b, k1b, k2b, 2.0f * acc[nb][3] - n1, kc + 1);
            }

            if (t + 1 < NTILES) CP_WAIT0();   // next tile landed
            __syncthreads();                  // all reads of cur done; nxt visible
        }

        // ---- merge across the 4 lanes of each quad ----
#pragma unroll
        for (int m = 1; m < 4; m <<= 1) {
            float od1 = __shfl_xor_sync(0xffffffffu, d1a, m);
            int   ok1 = __shfl_xor_sync(0xffffffffu, k1a, m);
            float od2 = __shfl_xor_sync(0xffffffffu, d2a, m);
            int   ok2 = __shfl_xor_sync(0xffffffffu, k2a, m);
            MERGE(d1a, k1a, d2a, k2a, od1, ok1, od2, ok2);
            od1 = __shfl_xor_sync(0xffffffffu, d1b, m);
            ok1 = __shfl_xor_sync(0xffffffffu, k1b, m);
            od2 = __shfl_xor_sync(0xffffffffu, d2b, m);
            ok2 = __shfl_xor_sync(0xffffffffu, k2b, m);
            MERGE(d1b, k1b, d2b, k2b, od1, ok1, od2, ok2);
        }

        // ---- finalize (quad leaders), fp64 recheck on near-ties ----
        if ((lane & 3) == 0) {
            int tA = wid * 16 + (lane >> 2);
#pragma unroll
            for (int h = 0; h < 2; h++) {
                int tok  = tA + h * 8;
                float f1 = h ? d1b : d1a, f2 = h ? d2b : d2a;
                int   c1 = h ? k1b : k1a, c2 = h ? k2b : k2a;
                int kbest = c1;
                if (f1 - f2 <= EPS) {
                    const float* r = R + tok * RSTR;
                    const float* e1p = es + (size_t)c1 * DD;
                    const float* e2p = es + (size_t)c2 * DD;
                    double q1 = 0.0, q2 = 0.0;
#pragma unroll 4
                    for (int d = 0; d < DD; d++) {
                        double rv = (double)r[d];
                        double a = (double)__ldg(e1p + d);
                        double b = (double)__ldg(e2p + d);
                        q1 += rv * a - 0.5 * a * a;
                        q2 += rv * b - 0.5 * b * b;
                    }
                    if (q2 > q1 || (q2 == q1 && c2 < c1)) kbest = c2;
                }
                bk[tok] = kbest;
            }
        }
        __syncthreads();

        // ---- emit codes + residual update ----
        if (tid < MT) {
            int kb2 = bk[tid];
            codes[(size_t)s * NTOK + tok0 + tid] = (float)kb2;
            const float4* eb = (const float4*)(es + (size_t)kb2 * DD);
            float4* rr = (float4*)(R + tid * RSTR);
#pragma unroll 8
            for (int j = 0; j < DD / 4; j++) {
                float4 rv = rr[j], ev = eb[j];
                rv.x -= ev.x; rv.y -= ev.y; rv.z -= ev.z; rv.w -= ev.w;
                rr[j] = rv;
            }
        }
        __syncthreads();
    }
}

// ---------------------------------------------------------------------------
extern "C" void kernel_launch(void* const* d_in, const int* in_sizes, int n_in,
                              void* d_out, int out_size) {
    const float* p0 = (const float*)d_in[0];
    const float* p1 = (const float*)d_in[1];
    const float* x;
    const float* embed;
    if (in_sizes[0] > in_sizes[1]) { x = p0; embed = p1; }
    else                           { x = p1; embed = p0; }
    float* codes = (float*)d_out;

    cudaFuncSetAttribute(rvq_mma_kernel,
                         cudaFuncAttributeMaxDynamicSharedMemorySize,
                         SMEM_BYTES);

    prep_kernel<<<(NQ * KK + 127) / 128, 128>>>(embed);
    rvq_mma_kernel<<<NTOK / MT, BLKT, SMEM_BYTES>>>(x, embed, codes);
}

// round 12
// speedup vs baseline: 2.0219x; 1.0091x over previous
#include <cuda_runtime.h>
#include <cuda_bf16.h>
#include <cstdint>

// EncodecQuantizer RVQ via mma.sync bf16x3 (emulated-fp32) GEMM.
// 512 threads: 16 warps = (8 row-groups) x (2 N-halves) per 128x64 tile.
// x [B,T,D] f32, embed [NQ,K,D] f32 -> codes [NQ,B*T] as float32.
#define BB    16
#define TT    4096
#define DD    128
#define NQ    8
#define KK    1024
#define NTOK  (BB * TT)        // 65536
#define MT    128              // tokens per block
#define NT    64               // codes per tile
#define NTILES (KK / NT)       // 16
#define BLKT  512              // 16 warps
#define RSTR  132              // R smem row stride (floats)
#define ASTR_B 528             // A/B smem row stride in BYTES (264 bf16)
#define EPS   3.0e-3f
#define FLTMIN (-3.402823466e+38f)

typedef unsigned long long u64;
typedef unsigned int u32;
typedef unsigned short u16;

// smem byte offsets
#define SM_A   0                                   // 128 x 528 B = 67584
#define SM_B0  (SM_A + MT * ASTR_B)                // 64 x 528 B  = 33792
#define SM_B1  (SM_B0 + NT * ASTR_B)
#define SM_R   (SM_B1 + NT * ASTR_B)               // 128 x 132 f32 = 67584
#define SM_N   (SM_R + MT * RSTR * 4)              // 1024 f32 = 4096
#define SM_BK  (SM_N + KK * 4)                     // 128 int = 512
#define SM_MG  (SM_BK + MT * 4)                    // merge scratch: 4 x 256 x 4
#define SMEM_BYTES (SM_MG + 4 * 256 * 4)           // 211456

__device__ float g_norms[NQ * KK];
// per codeword: e1[0..127] then e2[0..127] (bf16 hi/lo split)
__device__ __nv_bfloat16 g_esplit[(size_t)NQ * KK * 256];

// ---------------------------------------------------------------------------
__global__ void prep_kernel(const float* __restrict__ embed) {
    int k = blockIdx.x * blockDim.x + threadIdx.x;
    if (k >= NQ * KK) return;
    const float* e = embed + (size_t)k * DD;
    __nv_bfloat16* o = g_esplit + (size_t)k * 256;
    float s = 0.0f;
#pragma unroll 4
    for (int d = 0; d < DD; d++) {
        float v = e[d];
        s = fmaf(v, v, s);
        __nv_bfloat16 b1 = __float2bfloat16_rn(v);
        __nv_bfloat16 b2 = __float2bfloat16_rn(v - __bfloat162float(b1));
        o[d] = b1;
        o[DD + d] = b2;
    }
    g_norms[k] = s;
}

// ---------------------------------------------------------------------------
__device__ __forceinline__ u32 smem_u32(const void* p) {
    u32 a;
    asm("{ .reg .u64 t; cvta.to.shared.u64 t, %1; cvt.u32.u64 %0, t; }"
        : "=r"(a) : "l"(p));
    return a;
}
__device__ __forceinline__ void ldsm_x4(u32& r0, u32& r1, u32& r2, u32& r3,
                                        u32 addr) {
    asm volatile("ldmatrix.sync.aligned.m8n8.x4.shared.b16 {%0,%1,%2,%3}, [%4];"
                 : "=r"(r0), "=r"(r1), "=r"(r2), "=r"(r3) : "r"(addr));
}
__device__ __forceinline__ void mma_bf16(float* c, u32 a0, u32 a1, u32 a2,
                                         u32 a3, u32 b0, u32 b1) {
    asm volatile(
        "mma.sync.aligned.m16n8k16.row.col.f32.bf16.bf16.f32 "
        "{%0,%1,%2,%3}, {%4,%5,%6,%7}, {%8,%9}, {%0,%1,%2,%3};"
        : "+f"(c[0]), "+f"(c[1]), "+f"(c[2]), "+f"(c[3])
        : "r"(a0), "r"(a1), "r"(a2), "r"(a3), "r"(b0), "r"(b1));
}
__device__ __forceinline__ void cp16(u32 dst_smem, const void* src) {
    asm volatile("cp.async.cg.shared.global [%0], [%1], 16;"
                 :: "r"(dst_smem), "l"(src));
}
#define CP_COMMIT() asm volatile("cp.async.commit_group;" ::: "memory")
#define CP_WAIT0()  asm volatile("cp.async.wait_group 0;" ::: "memory")

// top-2 update, ascending-code encounter order assumed
#define UPD(d1, d2, q1, q2, dist, kc)                                    \
    do {                                                                 \
        if ((dist) > (d1)) { (d2) = (d1); (q2) = (q1); (d1) = (dist);    \
                             (q1) = (kc); }                              \
        else if ((dist) > (d2)) { (d2) = (dist); (q2) = (kc); }          \
    } while (0)

// merge other's top2 into ours; lower index wins ties
#define MERGE(d1, q1, d2, q2, od1, ok1, od2, ok2)                        \
    do {                                                                 \
        bool ob = ((od1) > (d1)) || ((od1) == (d1) && (ok1) < (q1));     \
        if (ob) {                                                        \
            bool sb = ((d1) > (od2)) || ((d1) == (od2) && (q1) < (ok2)); \
            (d2) = sb ? (d1) : (od2); (q2) = sb ? (q1) : (ok2);          \
            (d1) = (od1); (q1) = (ok1);                                  \
        } else {                                                         \
            bool sb = ((od1) > (d2)) || ((od1) == (d2) && (ok1) < (q2)); \
            if (sb) { (d2) = (od1); (q2) = (ok1); }                      \
        }                                                                \
    } while (0)

// ---------------------------------------------------------------------------
__global__ void __launch_bounds__(BLKT, 1)
rvq_mma_kernel(const float* __restrict__ x,
               const float* __restrict__ embed,
               float* __restrict__ codes) {
    extern __shared__ __align__(16) unsigned char smraw[];
    float* R   = (float*)(smraw + SM_R);
    float* SN  = (float*)(smraw + SM_N);
    int*   bk  = (int*)(smraw + SM_BK);
    float* MGd1 = (float*)(smraw + SM_MG);            // [2][128]
    float* MGd2 = MGd1 + 256;
    int*   MGk1 = (int*)(MGd2 + 256);
    int*   MGk2 = MGk1 + 256;
    const u32 smb = smem_u32(smraw);

    const int tid  = threadIdx.x;
    const int lane = tid & 31;
    const int wid  = tid >> 5;
    const int rowgrp = wid & 7;     // 16 token-rows each
    const int nhalf  = wid >> 3;    // 0: codes 0-31 of tile, 1: codes 32-63
    const int tok0 = blockIdx.x * MT;

    // ---- x -> R (4 threads per token) ----
    {
        int row = tid >> 2, q = tid & 3;
        const float4* xs = (const float4*)(x + (size_t)(tok0 + row) * DD +
                                           q * 32);
        float4* rd = (float4*)(R + row * RSTR + q * 32);
#pragma unroll
        for (int j = 0; j < 8; j++) rd[j] = xs[j];
    }
    __syncthreads();

    // lane addressing for ldmatrix
    const int a_row  = rowgrp * 16 + (lane & 15);
    const int a_cadd = ((lane >> 4) << 3) * 2;      // +8 cols (bytes)
    const int b_nloc = ((lane >> 4) << 3) | (lane & 7);
    const int b_cadd = (lane & 8) ? 16 : 0;         // +8 cols (bytes)
    const u32 buf_off[2] = {SM_B0, SM_B1};

    for (int s = 0; s < NQ; s++) {
        const float* es = embed + (size_t)s * KK * DD;
        const uint4* bsrc = (const uint4*)(g_esplit + (size_t)s * KK * 256);

        // stage norms
        for (int i = tid; i < KK; i += BLKT) SN[i] = g_norms[s * KK + i];

        // ---- A rebuild: bf16 split of residual (4 threads per token) ----
        {
            int row = tid >> 2, q = tid & 3;
            const float4* r = (const float4*)(R + row * RSTR + q * 32);
            unsigned char* abase = smraw + SM_A + row * ASTR_B + q * 64;
#pragma unroll
            for (int j = 0; j < 8; j++) {
                float4 v = r[j];
                float vf[4] = {v.x, v.y, v.z, v.w};
                u16 h1[4], h2[4];
#pragma unroll
                for (int q2 = 0; q2 < 4; q2++) {
                    __nv_bfloat16 b1 = __float2bfloat16_rn(vf[q2]);
                    __nv_bfloat16 b2 =
                        __float2bfloat16_rn(vf[q2] - __bfloat162float(b1));
                    h1[q2] = __bfloat16_as_ushort(b1);
                    h2[q2] = __bfloat16_as_ushort(b2);
                }
                uint2 w1 = make_uint2((u32)h1[0] | ((u32)h1[1] << 16),
                                      (u32)h1[2] | ((u32)h1[3] << 16));
                uint2 w2 = make_uint2((u32)h2[0] | ((u32)h2[1] << 16),
                                      (u32)h2[2] | ((u32)h2[3] << 16));
                *(uint2*)(abase + j * 8) = w1;         // r1 at col d
                *(uint2*)(abase + 256 + j * 8) = w2;   // r2 at col 128+d
            }
        }

        // ---- prologue: async-load B tile 0 ----
#pragma unroll
        for (int i = 0; i < 4; i++) {
            int idx = tid + i * BLKT;
            int r2 = idx >> 5, u2 = idx & 31;
            cp16(smb + SM_B0 + r2 * ASTR_B + u2 * 16,
                 bsrc + (size_t)r2 * 32 + u2);
        }
        CP_COMMIT();
        CP_WAIT0();
        __syncthreads();   // A + B0 visible

        // per-thread top-2 for rows (lane>>2) and (lane>>2)+8 of rowgrp
        float d1a = FLTMIN, d2a = FLTMIN, d1b = FLTMIN, d2b = FLTMIN;
        int   k1a = 0, k2a = 0, k1b = 0, k2b = 0;

        for (int t = 0; t < NTILES; t++) {
            const u32 cur = buf_off[t & 1];
            if (t + 1 < NTILES) {
                const uint4* src = bsrc + (size_t)(t + 1) * NT * 32;
                const u32 nxt = buf_off[(t + 1) & 1];
#pragma unroll
                for (int i = 0; i < 4; i++) {
                    int idx = tid + i * BLKT;
                    int r2 = idx >> 5, u2 = idx & 31;
                    cp16(smb + nxt + r2 * ASTR_B + u2 * 16,
                         src + (size_t)r2 * 32 + u2);
                }
                CP_COMMIT();
            }

            // ---- MMA on current tile: m16 x n32 per warp ----
            float acc[4][4];
#pragma unroll
            for (int i = 0; i < 4; i++) {
                acc[i][0] = 0.f; acc[i][1] = 0.f;
                acc[i][2] = 0.f; acc[i][3] = 0.f;
            }
#pragma unroll 4
            for (int ks = 0; ks < 24; ks++) {
                int acol = (ks < 8) ? ks * 16
                         : (ks < 16) ? (ks - 8) * 16 : 128 + (ks - 16) * 16;
                int bcol = (ks < 8) ? ks * 16
                         : (ks < 16) ? 128 + (ks - 8) * 16 : (ks - 16) * 16;
                u32 a0, a1, a2, a3;
                ldsm_x4(a0, a1, a2, a3,
                        smb + SM_A + a_row * ASTR_B + acol * 2 + a_cadd);
#pragma unroll
                for (int np = 0; np < 2; np++) {
                    u32 b0, b1, b2, b3;
                    ldsm_x4(b0, b1, b2, b3,
                            smb + cur +
                            (nhalf * 32 + np * 16 + b_nloc) * ASTR_B +
                            bcol * 2 + b_cadd);
                    mma_bf16(acc[np * 2 + 0], a0, a1, a2, a3, b0, b1);
                    mma_bf16(acc[np * 2 + 1], a0, a1, a2, a3, b2, b3);
                }
            }

            // ---- epilogue: distances + top-2 ----
#pragma unroll
            for (int nb = 0; nb < 4; nb++) {
                int kc = t * NT + nhalf * 32 + nb * 8 + (lane & 3) * 2;
                float n0 = SN[kc], n1 = SN[kc + 1];
                UPD(d1a, d2a, k1a, k2a, fmaf(2.0f, acc[nb][0], -n0), kc);
                UPD(d1a, d2a, k1a, k2a, fmaf(2.0f, acc[nb][1], -n1), kc + 1);
                UPD(d1b, d2b, k1b, k2b, fmaf(2.0f, acc[nb][2], -n0), kc);
                UPD(d1b, d2b, k1b, k2b, fmaf(2.0f, acc[nb][3], -n1), kc + 1);
            }

            if (t + 1 < NTILES) CP_WAIT0();
            __syncthreads();
        }

        // ---- merge across the 4 lanes of each quad ----
#pragma unroll
        for (int m = 1; m < 4; m <<= 1) {
            float od1 = __shfl_xor_sync(0xffffffffu, d1a, m);
            int   ok1 = __shfl_xor_sync(0xffffffffu, k1a, m);
            float od2 = __shfl_xor_sync(0xffffffffu, d2a, m);
            int   ok2 = __shfl_xor_sync(0xffffffffu, k2a, m);
            MERGE(d1a, k1a, d2a, k2a, od1, ok1, od2, ok2);
            od1 = __shfl_xor_sync(0xffffffffu, d1b, m);
            ok1 = __shfl_xor_sync(0xffffffffu, k1b, m);
            od2 = __shfl_xor_sync(0xffffffffu, d2b, m);
            ok2 = __shfl_xor_sync(0xffffffffu, k2b, m);
            MERGE(d1b, k1b, d2b, k2b, od1, ok1, od2, ok2);
        }

        // ---- quad leaders publish per-(token, nhalf) top-2 ----
        if ((lane & 3) == 0) {
            int tA = rowgrp * 16 + (lane >> 2);
            int iA = nhalf * MT + tA;
            MGd1[iA] = d1a; MGd2[iA] = d2a; MGk1[iA] = k1a; MGk2[iA] = k2a;
            int iB = iA + 8;
            MGd1[iB] = d1b; MGd2[iB] = d2b; MGk1[iB] = k1b; MGk2[iB] = k2b;
        }
        __syncthreads();

        // ---- final per-token merge + fp64 recheck (one thread per token) ----
        if (tid < MT) {
            float f1 = MGd1[tid], f2v = MGd2[tid];
            int   c1 = MGk1[tid], c2 = MGk2[tid];
            float o1 = MGd1[MT + tid], o2 = MGd2[MT + tid];
            int   oc1 = MGk1[MT + tid], oc2 = MGk2[MT + tid];
            MERGE(f1, c1, f2v, c2, o1, oc1, o2, oc2);
            int kbest = c1;
            if (f1 - f2v <= EPS) {
                const float* r = R + tid * RSTR;
                const float* e1p = es + (size_t)c1 * DD;
                const float* e2p = es + (size_t)c2 * DD;
                double q1 = 0.0, q2 = 0.0;
#pragma unroll 4
                for (int d = 0; d < DD; d++) {
                    double rv = (double)r[d];
                    double a = (double)__ldg(e1p + d);
                    double b = (double)__ldg(e2p + d);
                    q1 += rv * a - 0.5 * a * a;
                    q2 += rv * b - 0.5 * b * b;
                }
                if (q2 > q1 || (q2 == q1 && c2 < c1)) kbest = c2;
            }
            bk[tid] = kbest;
            codes[(size_t)s * NTOK + tok0 + tid] = (float)kbest;
        }
        __syncthreads();

        // ---- residual update (4 threads per token) ----
        {
            int row = tid >> 2, q = tid & 3;
            int kb2 = bk[row];
            const float4* eb =
                (const float4*)(es + (size_t)kb2 * DD + q * 32);
            float4* rr = (float4*)(R + row * RSTR + q * 32);
#pragma unroll
            for (int j = 0; j < 8; j++) {
                float4 rv = rr[j], ev = eb[j];
                rv.x -= ev.x; rv.y -= ev.y; rv.z -= ev.z; rv.w -= ev.w;
                rr[j] = rv;
            }
        }
        __syncthreads();
    }
}

// ---------------------------------------------------------------------------
extern "C" void kernel_launch(void* const* d_in, const int* in_sizes, int n_in,
                              void* d_out, int out_size) {
    const float* p0 = (const float*)d_in[0];
    const float* p1 = (const float*)d_in[1];
    const float* x;
    const float* embed;
    if (in_sizes[0] > in_sizes[1]) { x = p0; embed = p1; }
    else                           { x = p1; embed = p0; }
    float* codes = (float*)d_out;

    cudaFuncSetAttribute(rvq_mma_kernel,
                         cudaFuncAttributeMaxDynamicSharedMemorySize,
                         SMEM_BYTES);

    prep_kernel<<<(NQ * KK + 127) / 128, 128>>>(embed);
    rvq_mma_kernel<<<NTOK / MT, BLKT, SMEM_BYTES>>>(x, embed, codes);
}

// round 13
// speedup vs baseline: 2.1972x; 1.0867x over previous
#include <cuda_runtime.h>
#include <cuda_bf16.h>
#include <cstdint>

// EncodecQuantizer RVQ via mma.sync bf16x3 (emulated-fp32) GEMM.
// MT=64 tokens/block, 256 threads (8 warps = 4 rowgrps x 2 N-halves),
// residual in registers (4 threads/token), 2 blocks/SM.
// x [B,T,D] f32, embed [NQ,K,D] f32 -> codes [NQ,B*T] as float32.
#define BB    16
#define TT    4096
#define DD    128
#define NQ    8
#define KK    1024
#define NTOK  (BB * TT)        // 65536
#define MT    64               // tokens per block
#define NT    64               // codes per tile
#define NTILES (KK / NT)       // 16
#define BLKT  256              // 8 warps
#define ASTR_B 528             // A/B smem row stride in BYTES (264 bf16)
#define EPS   3.0e-3f
#define FLTMIN (-3.402823466e+38f)

typedef unsigned long long u64;
typedef unsigned int u32;
typedef unsigned short u16;

// smem byte offsets
#define SM_A   0                                  // 64 x 528 B = 33792
#define SM_B0  (SM_A + MT * ASTR_B)               // 33792
#define SM_B1  (SM_B0 + NT * ASTR_B)              // 67584
#define SM_N   (SM_B1 + NT * ASTR_B)              // 101376: 1024 f32
#define SM_MG  (SM_N + KK * 4)                    // 105472: 4 x 128 x 4B
#define SMEM_BYTES (SM_MG + 4 * 2 * MT * 4)       // 107520

__device__ float g_norms[NQ * KK];
// per codeword: e1[0..127] then e2[0..127] (bf16 hi/lo split)
__device__ __nv_bfloat16 g_esplit[(size_t)NQ * KK * 256];

// ---------------------------------------------------------------------------
__global__ void prep_kernel(const float* __restrict__ embed) {
    int k = blockIdx.x * blockDim.x + threadIdx.x;
    if (k >= NQ * KK) return;
    const float* e = embed + (size_t)k * DD;
    __nv_bfloat16* o = g_esplit + (size_t)k * 256;
    float s = 0.0f;
#pragma unroll 4
    for (int d = 0; d < DD; d++) {
        float v = e[d];
        s = fmaf(v, v, s);
        __nv_bfloat16 b1 = __float2bfloat16_rn(v);
        __nv_bfloat16 b2 = __float2bfloat16_rn(v - __bfloat162float(b1));
        o[d] = b1;
        o[DD + d] = b2;
    }
    g_norms[k] = s;
}

// ---------------------------------------------------------------------------
__device__ __forceinline__ u32 smem_u32(const void* p) {
    u32 a;
    asm("{ .reg .u64 t; cvta.to.shared.u64 t, %1; cvt.u32.u64 %0, t; }"
        : "=r"(a) : "l"(p));
    return a;
}
__device__ __forceinline__ void ldsm_x4(u32& r0, u32& r1, u32& r2, u32& r3,
                                        u32 addr) {
    asm volatile("ldmatrix.sync.aligned.m8n8.x4.shared.b16 {%0,%1,%2,%3}, [%4];"
                 : "=r"(r0), "=r"(r1), "=r"(r2), "=r"(r3) : "r"(addr));
}
__device__ __forceinline__ void mma_bf16(float* c, u32 a0, u32 a1, u32 a2,
                                         u32 a3, u32 b0, u32 b1) {
    asm volatile(
        "mma.sync.aligned.m16n8k16.row.col.f32.bf16.bf16.f32 "
        "{%0,%1,%2,%3}, {%4,%5,%6,%7}, {%8,%9}, {%0,%1,%2,%3};"
        : "+f"(c[0]), "+f"(c[1]), "+f"(c[2]), "+f"(c[3])
        : "r"(a0), "r"(a1), "r"(a2), "r"(a3), "r"(b0), "r"(b1));
}
__device__ __forceinline__ void cp16(u32 dst_smem, const void* src) {
    asm volatile("cp.async.cg.shared.global [%0], [%1], 16;"
                 :: "r"(dst_smem), "l"(src));
}
#define CP_COMMIT() asm volatile("cp.async.commit_group;" ::: "memory")
#define CP_WAIT0()  asm volatile("cp.async.wait_group 0;" ::: "memory")

#define UPD(d1, d2, q1, q2, dist, kc)                                    \
    do {                                                                 \
        if ((dist) > (d1)) { (d2) = (d1); (q2) = (q1); (d1) = (dist);    \
                             (q1) = (kc); }                              \
        else if ((dist) > (d2)) { (d2) = (dist); (q2) = (kc); }          \
    } while (0)

#define MERGE(d1, q1, d2, q2, od1, ok1, od2, ok2)                        \
    do {                                                                 \
        bool ob = ((od1) > (d1)) || ((od1) == (d1) && (ok1) < (q1));     \
        if (ob) {                                                        \
            bool sb = ((d1) > (od2)) || ((d1) == (od2) && (q1) < (ok2)); \
            (d2) = sb ? (d1) : (od2); (q2) = sb ? (q1) : (ok2);          \
            (d1) = (od1); (q1) = (ok1);                                  \
        } else {                                                         \
            bool sb = ((od1) > (d2)) || ((od1) == (d2) && (ok1) < (q2)); \
            if (sb) { (d2) = (od1); (q2) = (ok1); }                      \
        }                                                                \
    } while (0)

// ---------------------------------------------------------------------------
__global__ void __launch_bounds__(BLKT, 2)
rvq_mma_kernel(const float* __restrict__ x,
               const float* __restrict__ embed,
               float* __restrict__ codes) {
    extern __shared__ __align__(16) unsigned char smraw[];
    float* SN   = (float*)(smraw + SM_N);
    float* MGd1 = (float*)(smraw + SM_MG);            // [2][64]
    float* MGd2 = MGd1 + 2 * MT;
    int*   MGk1 = (int*)(MGd2 + 2 * MT);
    int*   MGk2 = MGk1 + 2 * MT;
    const u32 smb = smem_u32(smraw);

    const int tid  = threadIdx.x;
    const int lane = tid & 31;
    const int wid  = tid >> 5;
    const int rowgrp = wid & 3;     // 16 token-rows each
    const int nhalf  = wid >> 2;    // 0: codes 0-31 of tile, 1: codes 32-63
    const int tok0 = blockIdx.x * MT;
    const int row = tid >> 2;       // my token (0..63)
    const int q   = tid & 3;        // my quarter (32 dims)

    // ---- residual in registers: 32 floats per thread ----
    float4 rr[8];
    {
        const float4* xs = (const float4*)(x + (size_t)(tok0 + row) * DD +
                                           q * 32);
#pragma unroll
        for (int j = 0; j < 8; j++) rr[j] = xs[j];
    }

    // lane addressing for ldmatrix
    const int a_row  = rowgrp * 16 + (lane & 15);
    const int a_cadd = ((lane >> 4) << 3) * 2;      // +8 cols (bytes)
    const int b_nloc = ((lane >> 4) << 3) | (lane & 7);
    const int b_cadd = (lane & 8) ? 16 : 0;         // +8 cols (bytes)
    const u32 buf_off[2] = {SM_B0, SM_B1};

    for (int s = 0; s < NQ; s++) {
        const float* es = embed + (size_t)s * KK * DD;
        const uint4* bsrc = (const uint4*)(g_esplit + (size_t)s * KK * 256);

        // ---- issue async-load of B tile 0 early ----
#pragma unroll
        for (int i = 0; i < 8; i++) {
            int idx = tid + i * BLKT;
            int r2 = idx >> 5, u2 = idx & 31;
            cp16(smb + SM_B0 + r2 * ASTR_B + u2 * 16,
                 bsrc + (size_t)r2 * 32 + u2);
        }
        CP_COMMIT();

        // stage norms
        for (int i = tid; i < KK; i += BLKT) SN[i] = g_norms[s * KK + i];

        // ---- A rebuild from register residual (32 dims per thread) ----
        {
            unsigned char* abase = smraw + SM_A + row * ASTR_B + q * 64;
#pragma unroll
            for (int j = 0; j < 8; j++) {
                float4 v = rr[j];
                float vf[4] = {v.x, v.y, v.z, v.w};
                u16 h1[4], h2[4];
#pragma unroll
                for (int q2 = 0; q2 < 4; q2++) {
                    __nv_bfloat16 b1 = __float2bfloat16_rn(vf[q2]);
                    __nv_bfloat16 b2 =
                        __float2bfloat16_rn(vf[q2] - __bfloat162float(b1));
                    h1[q2] = __bfloat16_as_ushort(b1);
                    h2[q2] = __bfloat16_as_ushort(b2);
                }
                uint2 w1 = make_uint2((u32)h1[0] | ((u32)h1[1] << 16),
                                      (u32)h1[2] | ((u32)h1[3] << 16));
                uint2 w2 = make_uint2((u32)h2[0] | ((u32)h2[1] << 16),
                                      (u32)h2[2] | ((u32)h2[3] << 16));
                *(uint2*)(abase + j * 8) = w1;         // r1 at col d
                *(uint2*)(abase + 256 + j * 8) = w2;   // r2 at col 128+d
            }
        }
        CP_WAIT0();
        __syncthreads();   // A + B0 visible

        float d1a = FLTMIN, d2a = FLTMIN, d1b = FLTMIN, d2b = FLTMIN;
        int   k1a = 0, k2a = 0, k1b = 0, k2b = 0;

        for (int t = 0; t < NTILES; t++) {
            const u32 cur = buf_off[t & 1];
            if (t + 1 < NTILES) {
                const uint4* src = bsrc + (size_t)(t + 1) * NT * 32;
                const u32 nxt = buf_off[(t + 1) & 1];
#pragma unroll
                for (int i = 0; i < 8; i++) {
                    int idx = tid + i * BLKT;
                    int r2 = idx >> 5, u2 = idx & 31;
                    cp16(smb + nxt + r2 * ASTR_B + u2 * 16,
                         src + (size_t)r2 * 32 + u2);
                }
                CP_COMMIT();
            }

            // ---- MMA on current tile: m16 x n32 per warp ----
            float acc[4][4];
#pragma unroll
            for (int i = 0; i < 4; i++) {
                acc[i][0] = 0.f; acc[i][1] = 0.f;
                acc[i][2] = 0.f; acc[i][3] = 0.f;
            }
#pragma unroll 4
            for (int ks = 0; ks < 24; ks++) {
                int acol = (ks < 8) ? ks * 16
                         : (ks < 16) ? (ks - 8) * 16 : 128 + (ks - 16) * 16;
                int bcol = (ks < 8) ? ks * 16
                         : (ks < 16) ? 128 + (ks - 8) * 16 : (ks - 16) * 16;
                u32 a0, a1, a2, a3;
                ldsm_x4(a0, a1, a2, a3,
                        smb + SM_A + a_row * ASTR_B + acol * 2 + a_cadd);
#pragma unroll
                for (int np = 0; np < 2; np++) {
                    u32 b0, b1, b2, b3;
                    ldsm_x4(b0, b1, b2, b3,
                            smb + cur +
                            (nhalf * 32 + np * 16 + b_nloc) * ASTR_B +
                            bcol * 2 + b_cadd);
                    mma_bf16(acc[np * 2 + 0], a0, a1, a2, a3, b0, b1);
                    mma_bf16(acc[np * 2 + 1], a0, a1, a2, a3, b2, b3);
                }
            }

            // ---- epilogue: distances + top-2 ----
#pragma unroll
            for (int nb = 0; nb < 4; nb++) {
                int kc = t * NT + nhalf * 32 + nb * 8 + (lane & 3) * 2;
                float n0 = SN[kc], n1 = SN[kc + 1];
                UPD(d1a, d2a, k1a, k2a, fmaf(2.0f, acc[nb][0], -n0), kc);
                UPD(d1a, d2a, k1a, k2a, fmaf(2.0f, acc[nb][1], -n1), kc + 1);
                UPD(d1b, d2b, k1b, k2b, fmaf(2.0f, acc[nb][2], -n0), kc);
                UPD(d1b, d2b, k1b, k2b, fmaf(2.0f, acc[nb][3], -n1), kc + 1);
            }

            if (t + 1 < NTILES) CP_WAIT0();
            __syncthreads();
        }

        // ---- merge across the 4 lanes of each quad ----
#pragma unroll
        for (int m = 1; m < 4; m <<= 1) {
            float od1 = __shfl_xor_sync(0xffffffffu, d1a, m);
            int   ok1 = __shfl_xor_sync(0xffffffffu, k1a, m);
            float od2 = __shfl_xor_sync(0xffffffffu, d2a, m);
            int   ok2 = __shfl_xor_sync(0xffffffffu, k2a, m);
            MERGE(d1a, k1a, d2a, k2a, od1, ok1, od2, ok2);
            od1 = __shfl_xor_sync(0xffffffffu, d1b, m);
            ok1 = __shfl_xor_sync(0xffffffffu, k1b, m);
            od2 = __shfl_xor_sync(0xffffffffu, d2b, m);
            ok2 = __shfl_xor_sync(0xffffffffu, k2b, m);
            MERGE(d1b, k1b, d2b, k2b, od1, ok1, od2, ok2);
        }

        // ---- quad leaders publish per-(token, nhalf) top-2 ----
        if ((lane & 3) == 0) {
            int tA = rowgrp * 16 + (lane >> 2);
            int iA = nhalf * MT + tA;
            MGd1[iA] = d1a; MGd2[iA] = d2a; MGk1[iA] = k1a; MGk2[iA] = k2a;
            int iB = iA + 8;
            MGd1[iB] = d1b; MGd2[iB] = d2b; MGk1[iB] = k1b; MGk2[iB] = k2b;
        }
        __syncthreads();

        // ---- final merge + fp64 recheck (all 4 threads of a token) ----
        int kbest;
        {
            float f1 = MGd1[row], f2v = MGd2[row];
            int   c1 = MGk1[row], c2 = MGk2[row];
            float o1 = MGd1[MT + row], o2 = MGd2[MT + row];
            int   oc1 = MGk1[MT + row], oc2 = MGk2[MT + row];
            MERGE(f1, c1, f2v, c2, o1, oc1, o2, oc2);
            kbest = c1;
            if (f1 - f2v <= EPS) {
                // distributed exact recheck: each thread does its 32 dims,
                // butterfly-sum doubles within the quad (bit-identical in all
                // four lanes), then all four decide identically.
                const float* e1p = es + (size_t)c1 * DD + q * 32;
                const float* e2p = es + (size_t)c2 * DD + q * 32;
                double q1 = 0.0, q2 = 0.0;
#pragma unroll
                for (int j = 0; j < 8; j++) {
                    float4 v = rr[j];
                    float vf[4] = {v.x, v.y, v.z, v.w};
#pragma unroll
                    for (int c = 0; c < 4; c++) {
                        double rv = (double)vf[c];
                        double a = (double)__ldg(e1p + j * 4 + c);
                        double b = (double)__ldg(e2p + j * 4 + c);
                        q1 += rv * a - 0.5 * a * a;
                        q2 += rv * b - 0.5 * b * b;
                    }
                }
                unsigned mk = __activemask();
                q1 += __shfl_xor_sync(mk, q1, 1);
                q1 += __shfl_xor_sync(mk, q1, 2);
                q2 += __shfl_xor_sync(mk, q2, 1);
                q2 += __shfl_xor_sync(mk, q2, 2);
                if (q2 > q1 || (q2 == q1 && c2 < c1)) kbest = c2;
            }
            if (q == 0)
                codes[(size_t)s * NTOK + tok0 + row] = (float)kbest;
        }

        // ---- residual update in registers ----
        {
            const float4* eb =
                (const float4*)(es + (size_t)kbest * DD + q * 32);
#pragma unroll
            for (int j = 0; j < 8; j++) {
                float4 ev = eb[j];
                rr[j].x -= ev.x; rr[j].y -= ev.y;
                rr[j].z -= ev.z; rr[j].w -= ev.w;
            }
        }
        __syncthreads();   // MG reads done before next stage overwrites
    }
}

// ---------------------------------------------------------------------------
extern "C" void kernel_launch(void* const* d_in, const int* in_sizes, int n_in,
                              void* d_out, int out_size) {
    const float* p0 = (const float*)d_in[0];
    const float* p1 = (const float*)d_in[1];
    const float* x;
    const float* embed;
    if (in_sizes[0] > in_sizes[1]) { x = p0; embed = p1; }
    else                           { x = p1; embed = p0; }
    float* codes = (float*)d_out;

    cudaFuncSetAttribute(rvq_mma_kernel,
                         cudaFuncAttributeMaxDynamicSharedMemorySize,
                         SMEM_BYTES);

    prep_kernel<<<(NQ * KK + 127) / 128, 128>>>(embed);
    rvq_mma_kernel<<<NTOK / MT, BLKT, SMEM_BYTES>>>(x, embed, codes);
}

// round 15
// speedup vs baseline: 2.9184x; 1.3283x over previous
#include <cuda_runtime.h>
#include <cuda_bf16.h>
#include <cstdint>

// EncodecQuantizer RVQ via mma.sync bf16x3 (emulated-fp32) GEMM.
// K=384: [r1,r1,r2] x [e1,e2,e1]; only r2.e2 dropped (~1e-4) -> EPS=3e-3
// + fp64 near-tie recheck gives exact argmax. MT=64 tokens/block, 256 thr,
// 2 blocks/SM, residual in registers, fragment reuse across K-phases.
// x [B,T,D] f32, embed [NQ,K,D] f32 -> codes [NQ,B*T] as float32.
#define BB    16
#define TT    4096
#define DD    128
#define NQ    8
#define KK    1024
#define NTOK  (BB * TT)        // 65536
#define MT    64               // tokens per block
#define NT    64               // codes per tile
#define NTILES (KK / NT)       // 16
#define BLKT  256              // 8 warps
#define ASTR_A 528             // A smem row stride bytes (r1|r2: 256 bf16 + pad)
#define ASTR_B 528             // B smem row stride bytes (e1|e2: 256 bf16 + pad)
#define EPS   3.0e-3f
#define FLTMIN (-3.402823466e+38f)

typedef unsigned long long u64;
typedef unsigned int u32;
typedef unsigned short u16;

// smem byte offsets
#define SM_A   0                                  // 64 x 528 = 33792
#define SM_B0  (SM_A + MT * ASTR_A)               // 33792
#define SM_B1  (SM_B0 + NT * ASTR_B)              // 67584
#define SM_N   (SM_B1 + NT * ASTR_B)              // 101376: 1024 f32
#define SM_MG  (SM_N + KK * 4)                    // 105472
#define SMEM_BYTES (SM_MG + 4 * 2 * MT * 4)       // 107520

__device__ float g_norms[NQ * KK];
// per codeword: e1[0..127] then e2[0..127] (bf16 hi/lo split)
__device__ __nv_bfloat16 g_esplit[(size_t)NQ * KK * 256];

// ---------------------------------------------------------------------------
__global__ void prep_kernel(const float* __restrict__ embed) {
    int k = blockIdx.x * blockDim.x + threadIdx.x;
    if (k >= NQ * KK) return;
    const float* e = embed + (size_t)k * DD;
    __nv_bfloat16* o = g_esplit + (size_t)k * 256;
    float s = 0.0f;
#pragma unroll 4
    for (int d = 0; d < DD; d++) {
        float v = e[d];
        s = fmaf(v, v, s);
        __nv_bfloat16 b1 = __float2bfloat16_rn(v);
        __nv_bfloat16 b2 = __float2bfloat16_rn(v - __bfloat162float(b1));
        o[d] = b1;
        o[DD + d] = b2;
    }
    g_norms[k] = s;
}

// ---------------------------------------------------------------------------
__device__ __forceinline__ u32 smem_u32(const void* p) {
    u32 a;
    asm("{ .reg .u64 t; cvta.to.shared.u64 t, %1; cvt.u32.u64 %0, t; }"
        : "=r"(a) : "l"(p));
    return a;
}
__device__ __forceinline__ void ldsm_x4(u32& r0, u32& r1, u32& r2, u32& r3,
                                        u32 addr) {
    asm volatile("ldmatrix.sync.aligned.m8n8.x4.shared.b16 {%0,%1,%2,%3}, [%4];"
                 : "=r"(r0), "=r"(r1), "=r"(r2), "=r"(r3) : "r"(addr));
}
__device__ __forceinline__ void mma_bf16(float* c, const u32* a,
                                         u32 b0, u32 b1) {
    asm volatile(
        "mma.sync.aligned.m16n8k16.row.col.f32.bf16.bf16.f32 "
        "{%0,%1,%2,%3}, {%4,%5,%6,%7}, {%8,%9}, {%0,%1,%2,%3};"
        : "+f"(c[0]), "+f"(c[1]), "+f"(c[2]), "+f"(c[3])
        : "r"(a[0]), "r"(a[1]), "r"(a[2]), "r"(a[3]), "r"(b0), "r"(b1));
}
__device__ __forceinline__ void cp16(u32 dst_smem, const void* src) {
    asm volatile("cp.async.cg.shared.global [%0], [%1], 16;"
                 :: "r"(dst_smem), "l"(src));
}
#define CP_COMMIT() asm volatile("cp.async.commit_group;" ::: "memory")
#define CP_WAIT0()  asm volatile("cp.async.wait_group 0;" ::: "memory")

#define UPD(d1, d2, q1, q2, dist, kc)                                    \
    do {                                                                 \
        if ((dist) > (d1)) { (d2) = (d1); (q2) = (q1); (d1) = (dist);    \
                             (q1) = (kc); }                              \
        else if ((dist) > (d2)) { (d2) = (dist); (q2) = (kc); }          \
    } while (0)

#define MERGE(d1, q1, d2, q2, od1, ok1, od2, ok2)                        \
    do {                                                                 \
        bool ob = ((od1) > (d1)) || ((od1) == (d1) && (ok1) < (q1));     \
        if (ob) {                                                        \
            bool sb = ((d1) > (od2)) || ((d1) == (od2) && (q1) < (ok2)); \
            (d2) = sb ? (d1) : (od2); (q2) = sb ? (q1) : (ok2);          \
            (d1) = (od1); (q1) = (ok1);                                  \
        } else {                                                         \
            bool sb = ((od1) > (d2)) || ((od1) == (d2) && (ok1) < (q2)); \
            if (sb) { (d2) = (od1); (q2) = (ok1); }                      \
        }                                                                \
    } while (0)

// ---------------------------------------------------------------------------
__global__ void __launch_bounds__(BLKT, 2)
rvq_mma_kernel(const float* __restrict__ x,
               const float* __restrict__ embed,
               float* __restrict__ codes) {
    extern __shared__ __align__(16) unsigned char smraw[];
    float* SN   = (float*)(smraw + SM_N);
    float* MGd1 = (float*)(smraw + SM_MG);            // [2][64]
    float* MGd2 = MGd1 + 2 * MT;
    int*   MGk1 = (int*)(MGd2 + 2 * MT);
    int*   MGk2 = MGk1 + 2 * MT;
    const u32 smb = smem_u32(smraw);

    const int tid  = threadIdx.x;
    const int lane = tid & 31;
    const int wid  = tid >> 5;
    const int rowgrp = wid & 3;     // 16 token-rows each
    const int nhalf  = wid >> 2;    // 0: codes 0-31 of tile, 1: codes 32-63
    const int tok0 = blockIdx.x * MT;
    const int row = tid >> 2;       // my token (0..63)
    const int q   = tid & 3;        // my quarter (32 dims)

    // ---- residual in registers: 32 floats per thread ----
    float4 rr[8];
    {
        const float4* xs = (const float4*)(x + (size_t)(tok0 + row) * DD +
                                           q * 32);
#pragma unroll
        for (int j = 0; j < 8; j++) rr[j] = xs[j];
    }

    // lane addressing for ldmatrix
    const u32 a_addr = smb + SM_A +
        (rowgrp * 16 + (lane & 15)) * ASTR_A + (((lane >> 4) << 3) * 2);
    const int b_nloc = ((lane >> 4) << 3) | (lane & 7);
    const int b_cadd = (lane & 8) ? 16 : 0;
    const u32 b_lane_off = (nhalf * 32 + b_nloc) * ASTR_B + b_cadd;
    const u32 buf_off[2] = {SM_B0, SM_B1};

    for (int s = 0; s < NQ; s++) {
        const float* es = embed + (size_t)s * KK * DD;
        const uint4* bsrc = (const uint4*)(g_esplit + (size_t)s * KK * 256);

        // ---- issue async-load of B tile 0 early ----
#pragma unroll
        for (int i = 0; i < 8; i++) {
            int idx = tid + i * BLKT;
            int r2 = idx >> 5, u2 = idx & 31;
            cp16(smb + SM_B0 + r2 * ASTR_B + u2 * 16,
                 bsrc + (size_t)r2 * 32 + u2);
        }
        CP_COMMIT();

        // stage norms
        for (int i = tid; i < KK; i += BLKT) SN[i] = g_norms[s * KK + i];

        // ---- A rebuild: bf16 split r1 (cols 0-127) + r2 (cols 128-255) ----
        {
            unsigned char* abase = smraw + SM_A + row * ASTR_A + q * 64;
#pragma unroll
            for (int j = 0; j < 8; j++) {
                float4 v = rr[j];
                float vf[4] = {v.x, v.y, v.z, v.w};
                u16 h1[4], h2[4];
#pragma unroll
                for (int q2 = 0; q2 < 4; q2++) {
                    __nv_bfloat16 b1 = __float2bfloat16_rn(vf[q2]);
                    __nv_bfloat16 b2 =
                        __float2bfloat16_rn(vf[q2] - __bfloat162float(b1));
                    h1[q2] = __bfloat16_as_ushort(b1);
                    h2[q2] = __bfloat16_as_ushort(b2);
                }
                uint2 w1 = make_uint2((u32)h1[0] | ((u32)h1[1] << 16),
                                      (u32)h1[2] | ((u32)h1[3] << 16));
                uint2 w2 = make_uint2((u32)h2[0] | ((u32)h2[1] << 16),
                                      (u32)h2[2] | ((u32)h2[3] << 16));
                *(uint2*)(abase + j * 8) = w1;          // r1 at col d
                *(uint2*)(abase + 256 + j * 8) = w2;    // r2 at col 128+d
            }
        }
        CP_WAIT0();
        __syncthreads();   // A + B0 visible

        float d1a = FLTMIN, d2a = FLTMIN, d1b = FLTMIN, d2b = FLTMIN;
        int   k1a = 0, k2a = 0, k1b = 0, k2b = 0;

        for (int t = 0; t < NTILES; t++) {
            const u32 cur = buf_off[t & 1];
            if (t + 1 < NTILES) {
                const uint4* src = bsrc + (size_t)(t + 1) * NT * 32;
                const u32 nxt = buf_off[(t + 1) & 1];
#pragma unroll
                for (int i = 0; i < 8; i++) {
                    int idx = tid + i * BLKT;
                    int r2 = idx >> 5, u2 = idx & 31;
                    cp16(smb + nxt + r2 * ASTR_B + u2 * 16,
                         src + (size_t)r2 * 32 + u2);
                }
                CP_COMMIT();
            }

            // ---- MMA: K=384 over 24 fully-unrolled ksteps, m16 x n32/warp.
            // Phase 1 per ks: load a1 (r1, kept), a2 (r2, transient), b=e1;
            //   both a1 and a2 multiply the SAME b fragments.
            // Phase 2 per ks: load b=e2; reuse cached a1.
            float acc[4][4];
#pragma unroll
            for (int i = 0; i < 4; i++) {
                acc[i][0] = 0.f; acc[i][1] = 0.f;
                acc[i][2] = 0.f; acc[i][3] = 0.f;
            }
            u32 a1[8][4];
            const u32 bbase = smb + cur + b_lane_off;
#pragma unroll
            for (int ks = 0; ks < 8; ks++) {
                u32 a2[4];
                ldsm_x4(a1[ks][0], a1[ks][1], a1[ks][2], a1[ks][3],
                        a_addr + ks * 32);
                ldsm_x4(a2[0], a2[1], a2[2], a2[3],
                        a_addr + 256 + ks * 32);
                u32 b0, b1, b2, b3;
                ldsm_x4(b0, b1, b2, b3, bbase + ks * 32);           // e1 grp0
                mma_bf16(acc[0], a1[ks], b0, b1);
                mma_bf16(acc[1], a1[ks], b2, b3);
                mma_bf16(acc[0], a2, b0, b1);
                mma_bf16(acc[1], a2, b2, b3);
                ldsm_x4(b0, b1, b2, b3,
                        bbase + 16 * ASTR_B + ks * 32);             // e1 grp1
                mma_bf16(acc[2], a1[ks], b0, b1);
                mma_bf16(acc[3], a1[ks], b2, b3);
                mma_bf16(acc[2], a2, b0, b1);
                mma_bf16(acc[3], a2, b2, b3);
            }
#pragma unroll
            for (int ks = 0; ks < 8; ks++) {
                u32 b0, b1, b2, b3;
                ldsm_x4(b0, b1, b2, b3, bbase + 256 + ks * 32);     // e2 grp0
                mma_bf16(acc[0], a1[ks], b0, b1);
                mma_bf16(acc[1], a1[ks], b2, b3);
                ldsm_x4(b0, b1, b2, b3,
                        bbase + 16 * ASTR_B + 256 + ks * 32);       // e2 grp1
                mma_bf16(acc[2], a1[ks], b0, b1);
                mma_bf16(acc[3], a1[ks], b2, b3);
            }

            // ---- epilogue: distances + top-2 ----
#pragma unroll
            for (int nb = 0; nb < 4; nb++) {
                int kc = t * NT + nhalf * 32 + nb * 8 + (lane & 3) * 2;
                float n0 = SN[kc], n1 = SN[kc + 1];
                UPD(d1a, d2a, k1a, k2a, fmaf(2.0f, acc[nb][0], -n0), kc);
                UPD(d1a, d2a, k1a, k2a, fmaf(2.0f, acc[nb][1], -n1), kc + 1);
                UPD(d1b, d2b, k1b, k2b, fmaf(2.0f, acc[nb][2], -n0), kc);
                UPD(d1b, d2b, k1b, k2b, fmaf(2.0f, acc[nb][3], -n1), kc + 1);
            }

            if (t + 1 < NTILES) CP_WAIT0();
            __syncthreads();
        }

        // ---- merge across the 4 lanes of each quad ----
#pragma unroll
        for (int m = 1; m < 4; m <<= 1) {
            float od1 = __shfl_xor_sync(0xffffffffu, d1a, m);
            int   ok1 = __shfl_xor_sync(0xffffffffu, k1a, m);
            float od2 = __shfl_xor_sync(0xffffffffu, d2a, m);
            int   ok2 = __shfl_xor_sync(0xffffffffu, k2a, m);
            MERGE(d1a, k1a, d2a, k2a, od1, ok1, od2, ok2);
            od1 = __shfl_xor_sync(0xffffffffu, d1b, m);
            ok1 = __shfl_xor_sync(0xffffffffu, k1b, m);
            od2 = __shfl_xor_sync(0xffffffffu, d2b, m);
            ok2 = __shfl_xor_sync(0xffffffffu, k2b, m);
            MERGE(d1b, k1b, d2b, k2b, od1, ok1, od2, ok2);
        }

        // ---- quad leaders publish per-(token, nhalf) top-2 ----
        if ((lane & 3) == 0) {
            int tA = rowgrp * 16 + (lane >> 2);
            int iA = nhalf * MT + tA;
            MGd1[iA] = d1a; MGd2[iA] = d2a; MGk1[iA] = k1a; MGk2[iA] = k2a;
            int iB = iA + 8;
            MGd1[iB] = d1b; MGd2[iB] = d2b; MGk1[iB] = k1b; MGk2[iB] = k2b;
        }
        __syncthreads();

        // ---- final merge + fp64 recheck (all 4 threads of a token) ----
        int kbest;
        {
            float f1 = MGd1[row], f2v = MGd2[row];
            int   c1 = MGk1[row], c2 = MGk2[row];
            float o1 = MGd1[MT + row], o2 = MGd2[MT + row];
            int   oc1 = MGk1[MT + row], oc2 = MGk2[MT + row];
            MERGE(f1, c1, f2v, c2, o1, oc1, o2, oc2);
            kbest = c1;
            if (f1 - f2v <= EPS) {
                const float* e1p = es + (size_t)c1 * DD + q * 32;
                const float* e2p = es + (size_t)c2 * DD + q * 32;
                double q1 = 0.0, q2 = 0.0;
#pragma unroll
                for (int j = 0; j < 8; j++) {
                    float4 v = rr[j];
                    float vf[4] = {v.x, v.y, v.z, v.w};
#pragma unroll
                    for (int c = 0; c < 4; c++) {
                        double rv = (double)vf[c];
                        double a = (double)__ldg(e1p + j * 4 + c);
                        double b = (double)__ldg(e2p + j * 4 + c);
                        q1 += rv * a - 0.5 * a * a;
                        q2 += rv * b - 0.5 * b * b;
                    }
                }
                unsigned mk = __activemask();
                q1 += __shfl_xor_sync(mk, q1, 1);
                q1 += __shfl_xor_sync(mk, q1, 2);
                q2 += __shfl_xor_sync(mk, q2, 1);
                q2 += __shfl_xor_sync(mk, q2, 2);
                if (q2 > q1 || (q2 == q1 && c2 < c1)) kbest = c2;
            }
            if (q == 0)
                codes[(size_t)s * NTOK + tok0 + row] = (float)kbest;
        }

        // ---- residual update in registers (fp32 exact) ----
        {
            const float4* eb =
                (const float4*)(es + (size_t)kbest * DD + q * 32);
#pragma unroll
            for (int j = 0; j < 8; j++) {
                float4 ev = eb[j];
                rr[j].x -= ev.x; rr[j].y -= ev.y;
                rr[j].z -= ev.z; rr[j].w -= ev.w;
            }
        }
        __syncthreads();   // MG reads done before next stage overwrites
    }
}

// ---------------------------------------------------------------------------
extern "C" void kernel_launch(void* const* d_in, const int* in_sizes, int n_in,
                              void* d_out, int out_size) {
    const float* p0 = (const float*)d_in[0];
    const float* p1 = (const float*)d_in[1];
    const float* x;
    const float* embed;
    if (in_sizes[0] > in_sizes[1]) { x = p0; embed = p1; }
    else                           { x = p1; embed = p0; }
    float* codes = (float*)d_out;

    cudaFuncSetAttribute(rvq_mma_kernel,
                         cudaFuncAttributeMaxDynamicSharedMemorySize,
                         SMEM_BYTES);

    prep_kernel<<<(NQ * KK + 127) / 128, 128>>>(embed);
    rvq_mma_kernel<<<NTOK / MT, BLKT, SMEM_BYTES>>>(x, embed, codes);
}

// round 16
// speedup vs baseline: 3.0389x; 1.0413x over previous
#include <cuda_runtime.h>
#include <cuda_bf16.h>
#include <cstdint>

// EncodecQuantizer RVQ via mma.sync bf16x3 (emulated-fp32) GEMM.
// K=384: [r1,r1,r2] x [e1,e2,e1]; only r2.e2 dropped (~1e-4) -> EPS=3e-3
// + fp64 near-tie recheck gives exact argmax. MT=64 tokens/block, NT=32
// codes/tile, 256 threads, 3 blocks/SM (interleaved ksteps keep regs < 85).
// x [B,T,D] f32, embed [NQ,K,D] f32 -> codes [NQ,B*T] as float32.
#define BB    16
#define TT    4096
#define DD    128
#define NQ    8
#define KK    1024
#define NTOK  (BB * TT)        // 65536
#define MT    64               // tokens per block
#define NT    32               // codes per tile
#define NTILES (KK / NT)       // 32
#define BLKT  256              // 8 warps
#define ASTR_A 528             // A smem row stride bytes (r1|r2: 256 bf16 + pad)
#define ASTR_B 528             // B smem row stride bytes (e1|e2: 256 bf16 + pad)
#define EPS   3.0e-3f
#define FLTMIN (-3.402823466e+38f)

typedef unsigned long long u64;
typedef unsigned int u32;
typedef unsigned short u16;

// smem byte offsets
#define SM_A   0                                  // 64 x 528 = 33792
#define SM_B0  (SM_A + MT * ASTR_A)               // 33792
#define SM_B1  (SM_B0 + NT * ASTR_B)              // 50688
#define SM_N   (SM_B1 + NT * ASTR_B)              // 67584: 1024 f32
#define SM_MG  (SM_N + KK * 4)                    // 71680: 4 x 128 x 4B
#define SMEM_BYTES (SM_MG + 4 * 2 * MT * 4)       // 73728 (72 KB -> 3/SM)

__device__ float g_norms[NQ * KK];
// per codeword: e1[0..127] then e2[0..127] (bf16 hi/lo split)
__device__ __nv_bfloat16 g_esplit[(size_t)NQ * KK * 256];

// ---------------------------------------------------------------------------
__global__ void prep_kernel(const float* __restrict__ embed) {
    int k = blockIdx.x * blockDim.x + threadIdx.x;
    if (k >= NQ * KK) return;
    const float* e = embed + (size_t)k * DD;
    __nv_bfloat16* o = g_esplit + (size_t)k * 256;
    float s = 0.0f;
#pragma unroll 4
    for (int d = 0; d < DD; d++) {
        float v = e[d];
        s = fmaf(v, v, s);
        __nv_bfloat16 b1 = __float2bfloat16_rn(v);
        __nv_bfloat16 b2 = __float2bfloat16_rn(v - __bfloat162float(b1));
        o[d] = b1;
        o[DD + d] = b2;
    }
    g_norms[k] = s;
}

// ---------------------------------------------------------------------------
__device__ __forceinline__ u32 smem_u32(const void* p) {
    u32 a;
    asm("{ .reg .u64 t; cvta.to.shared.u64 t, %1; cvt.u32.u64 %0, t; }"
        : "=r"(a) : "l"(p));
    return a;
}
__device__ __forceinline__ void ldsm_x4(u32& r0, u32& r1, u32& r2, u32& r3,
                                        u32 addr) {
    asm volatile("ldmatrix.sync.aligned.m8n8.x4.shared.b16 {%0,%1,%2,%3}, [%4];"
                 : "=r"(r0), "=r"(r1), "=r"(r2), "=r"(r3) : "r"(addr));
}
__device__ __forceinline__ void mma_bf16(float* c, const u32* a,
                                         u32 b0, u32 b1) {
    asm volatile(
        "mma.sync.aligned.m16n8k16.row.col.f32.bf16.bf16.f32 "
        "{%0,%1,%2,%3}, {%4,%5,%6,%7}, {%8,%9}, {%0,%1,%2,%3};"
        : "+f"(c[0]), "+f"(c[1]), "+f"(c[2]), "+f"(c[3])
        : "r"(a[0]), "r"(a[1]), "r"(a[2]), "r"(a[3]), "r"(b0), "r"(b1));
}
__device__ __forceinline__ void cp16(u32 dst_smem, const void* src) {
    asm volatile("cp.async.cg.shared.global [%0], [%1], 16;"
                 :: "r"(dst_smem), "l"(src));
}
#define CP_COMMIT() asm volatile("cp.async.commit_group;" ::: "memory")
#define CP_WAIT0()  asm volatile("cp.async.wait_group 0;" ::: "memory")

#define UPD(d1, d2, q1, q2, dist, kc)                                    \
    do {                                                                 \
        if ((dist) > (d1)) { (d2) = (d1); (q2) = (q1); (d1) = (dist);    \
                             (q1) = (kc); }                              \
        else if ((dist) > (d2)) { (d2) = (dist); (q2) = (kc); }          \
    } while (0)

#define MERGE(d1, q1, d2, q2, od1, ok1, od2, ok2)                        \
    do {                                                                 \
        bool ob = ((od1) > (d1)) || ((od1) == (d1) && (ok1) < (q1));     \
        if (ob) {                                                        \
            bool sb = ((d1) > (od2)) || ((d1) == (od2) && (q1) < (ok2)); \
            (d2) = sb ? (d1) : (od2); (q2) = sb ? (q1) : (ok2);          \
            (d1) = (od1); (q1) = (ok1);                                  \
        } else {                                                         \
            bool sb = ((od1) > (d2)) || ((od1) == (d2) && (ok1) < (q2)); \
            if (sb) { (d2) = (od1); (q2) = (ok1); }                      \
        }                                                                \
    } while (0)

// ---------------------------------------------------------------------------
__global__ void __launch_bounds__(BLKT, 3)
rvq_mma_kernel(const float* __restrict__ x,
               const float* __restrict__ embed,
               float* __restrict__ codes) {
    extern __shared__ __align__(16) unsigned char smraw[];
    float* SN   = (float*)(smraw + SM_N);
    float* MGd1 = (float*)(smraw + SM_MG);            // [2][64]
    float* MGd2 = MGd1 + 2 * MT;
    int*   MGk1 = (int*)(MGd2 + 2 * MT);
    int*   MGk2 = MGk1 + 2 * MT;
    const u32 smb = smem_u32(smraw);

    const int tid  = threadIdx.x;
    const int lane = tid & 31;
    const int wid  = tid >> 5;
    const int rowgrp = wid & 3;     // 16 token-rows each
    const int nhalf  = wid >> 2;    // 0: codes 0-15 of tile, 1: codes 16-31
    const int tok0 = blockIdx.x * MT;
    const int row = tid >> 2;       // my token (0..63)
    const int q   = tid & 3;        // my quarter (32 dims)

    // ---- residual in registers: 32 floats per thread ----
    float4 rr[8];
    {
        const float4* xs = (const float4*)(x + (size_t)(tok0 + row) * DD +
                                           q * 32);
#pragma unroll
        for (int j = 0; j < 8; j++) rr[j] = xs[j];
    }

    // lane addressing for ldmatrix
    const u32 a_addr = smb + SM_A +
        (rowgrp * 16 + (lane & 15)) * ASTR_A + (((lane >> 4) << 3) * 2);
    const int b_nloc = ((lane >> 4) << 3) | (lane & 7);
    const int b_cadd = (lane & 8) ? 16 : 0;
    const u32 b_lane_off = (nhalf * 16 + b_nloc) * ASTR_B + b_cadd;
    const u32 buf_off[2] = {SM_B0, SM_B1};

    for (int s = 0; s < NQ; s++) {
        const float* es = embed + (size_t)s * KK * DD;
        const uint4* bsrc = (const uint4*)(g_esplit + (size_t)s * KK * 256);

        // ---- issue async-load of B tile 0 early (32 rows x 512B) ----
#pragma unroll
        for (int i = 0; i < 4; i++) {
            int idx = tid + i * BLKT;
            int r2 = idx >> 5, u2 = idx & 31;
            cp16(smb + SM_B0 + r2 * ASTR_B + u2 * 16,
                 bsrc + (size_t)r2 * 32 + u2);
        }
        CP_COMMIT();

        // stage norms
        for (int i = tid; i < KK; i += BLKT) SN[i] = g_norms[s * KK + i];

        // ---- A rebuild: bf16 split r1 (cols 0-127) + r2 (cols 128-255) ----
        {
            unsigned char* abase = smraw + SM_A + row * ASTR_A + q * 64;
#pragma unroll
            for (int j = 0; j < 8; j++) {
                float4 v = rr[j];
                float vf[4] = {v.x, v.y, v.z, v.w};
                u16 h1[4], h2[4];
#pragma unroll
                for (int q2 = 0; q2 < 4; q2++) {
                    __nv_bfloat16 b1 = __float2bfloat16_rn(vf[q2]);
                    __nv_bfloat16 b2 =
                        __float2bfloat16_rn(vf[q2] - __bfloat162float(b1));
                    h1[q2] = __bfloat16_as_ushort(b1);
                    h2[q2] = __bfloat16_as_ushort(b2);
                }
                uint2 w1 = make_uint2((u32)h1[0] | ((u32)h1[1] << 16),
                                      (u32)h1[2] | ((u32)h1[3] << 16));
                uint2 w2 = make_uint2((u32)h2[0] | ((u32)h2[1] << 16),
                                      (u32)h2[2] | ((u32)h2[3] << 16));
                *(uint2*)(abase + j * 8) = w1;          // r1 at col d
                *(uint2*)(abase + 256 + j * 8) = w2;    // r2 at col 128+d
            }
        }
        CP_WAIT0();
        __syncthreads();   // A + B0 visible

        float d1a = FLTMIN, d2a = FLTMIN, d1b = FLTMIN, d2b = FLTMIN;
        int   k1a = 0, k2a = 0, k1b = 0, k2b = 0;

        for (int t = 0; t < NTILES; t++) {
            const u32 cur = buf_off[t & 1];
            if (t + 1 < NTILES) {
                const uint4* src = bsrc + (size_t)(t + 1) * NT * 32;
                const u32 nxt = buf_off[(t + 1) & 1];
#pragma unroll
                for (int i = 0; i < 4; i++) {
                    int idx = tid + i * BLKT;
                    int r2 = idx >> 5, u2 = idx & 31;
                    cp16(smb + nxt + r2 * ASTR_B + u2 * 16,
                         src + (size_t)r2 * 32 + u2);
                }
                CP_COMMIT();
            }

            // ---- MMA: K=384, 8 interleaved ksteps, m16 x n16 per warp.
            // Per kstep: a1 (r1), a2 (r2), b_e1: a1.e1, a2.e1; then b_e2:
            // a1.e2 reusing a1 within the kstep (no cached-A register array).
            float acc[2][4];
            acc[0][0] = 0.f; acc[0][1] = 0.f; acc[0][2] = 0.f; acc[0][3] = 0.f;
            acc[1][0] = 0.f; acc[1][1] = 0.f; acc[1][2] = 0.f; acc[1][3] = 0.f;
            const u32 bbase = smb + cur + b_lane_off;
#pragma unroll
            for (int ks = 0; ks < 8; ks++) {
                u32 a1[4], a2[4];
                ldsm_x4(a1[0], a1[1], a1[2], a1[3], a_addr + ks * 32);
                ldsm_x4(a2[0], a2[1], a2[2], a2[3], a_addr + 256 + ks * 32);
                u32 b0, b1, b2, b3;
                ldsm_x4(b0, b1, b2, b3, bbase + ks * 32);          // e1
                mma_bf16(acc[0], a1, b0, b1);
                mma_bf16(acc[1], a1, b2, b3);
                mma_bf16(acc[0], a2, b0, b1);
                mma_bf16(acc[1], a2, b2, b3);
                ldsm_x4(b0, b1, b2, b3, bbase + 256 + ks * 32);    // e2
                mma_bf16(acc[0], a1, b0, b1);
                mma_bf16(acc[1], a1, b2, b3);
            }

            // ---- epilogue: distances + top-2 ----
#pragma unroll
            for (int nb = 0; nb < 2; nb++) {
                int kc = t * NT + nhalf * 16 + nb * 8 + (lane & 3) * 2;
                float n0 = SN[kc], n1 = SN[kc + 1];
                UPD(d1a, d2a, k1a, k2a, fmaf(2.0f, acc[nb][0], -n0), kc);
                UPD(d1a, d2a, k1a, k2a, fmaf(2.0f, acc[nb][1], -n1), kc + 1);
                UPD(d1b, d2b, k1b, k2b, fmaf(2.0f, acc[nb][2], -n0), kc);
                UPD(d1b, d2b, k1b, k2b, fmaf(2.0f, acc[nb][3], -n1), kc + 1);
            }

            if (t + 1 < NTILES) CP_WAIT0();
            __syncthreads();
        }

        // ---- merge across the 4 lanes of each quad ----
#pragma unroll
        for (int m = 1; m < 4; m <<= 1) {
            float od1 = __shfl_xor_sync(0xffffffffu, d1a, m);
            int   ok1 = __shfl_xor_sync(0xffffffffu, k1a, m);
            float od2 = __shfl_xor_sync(0xffffffffu, d2a, m);
            int   ok2 = __shfl_xor_sync(0xffffffffu, k2a, m);
            MERGE(d1a, k1a, d2a, k2a, od1, ok1, od2, ok2);
            od1 = __shfl_xor_sync(0xffffffffu, d1b, m);
            ok1 = __shfl_xor_sync(0xffffffffu, k1b, m);
            od2 = __shfl_xor_sync(0xffffffffu, d2b, m);
            ok2 = __shfl_xor_sync(0xffffffffu, k2b, m);
            MERGE(d1b, k1b, d2b, k2b, od1, ok1, od2, ok2);
        }

        // ---- quad leaders publish per-(token, nhalf) top-2 ----
        if ((lane & 3) == 0) {
            int tA = rowgrp * 16 + (lane >> 2);
            int iA = nhalf * MT + tA;
            MGd1[iA] = d1a; MGd2[iA] = d2a; MGk1[iA] = k1a; MGk2[iA] = k2a;
            int iB = iA + 8;
            MGd1[iB] = d1b; MGd2[iB] = d2b; MGk1[iB] = k1b; MGk2[iB] = k2b;
        }
        __syncthreads();

        // ---- final merge + fp64 recheck (all 4 threads of a token) ----
        int kbest;
        {
            float f1 = MGd1[row], f2v = MGd2[row];
            int   c1 = MGk1[row], c2 = MGk2[row];
            float o1 = MGd1[MT + row], o2 = MGd2[MT + row];
            int   oc1 = MGk1[MT + row], oc2 = MGk2[MT + row];
            MERGE(f1, c1, f2v, c2, o1, oc1, o2, oc2);
            kbest = c1;
            if (f1 - f2v <= EPS) {
                const float* e1p = es + (size_t)c1 * DD + q * 32;
                const float* e2p = es + (size_t)c2 * DD + q * 32;
                double q1 = 0.0, q2 = 0.0;
#pragma unroll
                for (int j = 0; j < 8; j++) {
                    float4 v = rr[j];
                    float vf[4] = {v.x, v.y, v.z, v.w};
#pragma unroll
                    for (int c = 0; c < 4; c++) {
                        double rv = (double)vf[c];
                        double a = (double)__ldg(e1p + j * 4 + c);
                        double b = (double)__ldg(e2p + j * 4 + c);
                        q1 += rv * a - 0.5 * a * a;
                        q2 += rv * b - 0.5 * b * b;
                    }
                }
                unsigned mk = __activemask();
                q1 += __shfl_xor_sync(mk, q1, 1);
                q1 += __shfl_xor_sync(mk, q1, 2);
                q2 += __shfl_xor_sync(mk, q2, 1);
                q2 += __shfl_xor_sync(mk, q2, 2);
                if (q2 > q1 || (q2 == q1 && c2 < c1)) kbest = c2;
            }
            if (q == 0)
                codes[(size_t)s * NTOK + tok0 + row] = (float)kbest;
        }

        // ---- residual update in registers (fp32 exact) ----
        {
            const float4* eb =
                (const float4*)(es + (size_t)kbest * DD + q * 32);
#pragma unroll
            for (int j = 0; j < 8; j++) {
                float4 ev = eb[j];
                rr[j].x -= ev.x; rr[j].y -= ev.y;
                rr[j].z -= ev.z; rr[j].w -= ev.w;
            }
        }
        __syncthreads();   // MG reads done before next stage overwrites
    }
}

// ---------------------------------------------------------------------------
extern "C" void kernel_launch(void* const* d_in, const int* in_sizes, int n_in,
                              void* d_out, int out_size) {
    const float* p0 = (const float*)d_in[0];
    const float* p1 = (const float*)d_in[1];
    const float* x;
    const float* embed;
    if (in_sizes[0] > in_sizes[1]) { x = p0; embed = p1; }
    else                           { x = p1; embed = p0; }
    float* codes = (float*)d_out;

    cudaFuncSetAttribute(rvq_mma_kernel,
                         cudaFuncAttributeMaxDynamicSharedMemorySize,
                         SMEM_BYTES);

    prep_kernel<<<(NQ * KK + 127) / 128, 128>>>(embed);
    rvq_mma_kernel<<<NTOK / MT, BLKT, SMEM_BYTES>>>(x, embed, codes);
}